// round 13
// baseline (speedup 1.0000x reference)
#include <cuda_runtime.h>
#include <cuda_fp16.h>
#include <cstdint>

#define N_PIX 1600
#define CCH   512
#define CORR  256
#define BATCH 16
#define NTILE 50    // N_PIX / 32

#define ESCALE 4096.0f
#define INV_ESCALE (1.0f / 4096.0f)

// ---------------- scratch (static __device__ arrays; allocation-free) -------
__device__ __half g_inTe  [BATCH * N_PIX * CCH];           // exemplar^T [p][c]
__device__ __half g_inTq  [BATCH * N_PIX * CCH];           // query^T    [p][c]
__device__ __half g_qcorr [BATCH * N_PIX * CORR];
__device__ __half g_ecorr [BATCH * N_PIX * CORR];
__device__ __half g_E     [(long)BATCH * N_PIX * N_PIX];   // exp(A)   82 MB
__device__ __half g_Et    [(long)BATCH * N_PIX * N_PIX];   // E^T      82 MB
__device__ float  g_prow  [BATCH * NTILE * N_PIX];
__device__ float  g_pcol  [BATCH * NTILE * N_PIX];
__device__ float  g_rsE   [BATCH * N_PIX];                 // 1/rowsum(E)
__device__ float  g_rsEt  [BATCH * N_PIX];                 // 1/colsum(E)
__device__ __half g_esc   [BATCH * CCH * N_PIX];           // exemplar*invColsum*4096
__device__ __half g_qsc   [BATCH * CCH * N_PIX];           // query*invRowsum*4096
__device__ __half g_attTe [BATCH * N_PIX * CCH];
__device__ __half g_attTq [BATCH * N_PIX * CCH];
__device__ __half g_wT    [2 * 9 * CCH * CCH];             // [which][kyx][o][c]
__device__ __half g_w1    [2 * CORR * CCH];

// ---------------- helpers -----------------------------------------------------
__device__ __forceinline__ void mma16(float4& d, const uint32_t a[4],
                                      const uint32_t b[2]) {
    asm volatile(
        "mma.sync.aligned.m16n8k16.row.col.f32.f16.f16.f32 "
        "{%0,%1,%2,%3}, {%4,%5,%6,%7}, {%8,%9}, {%0,%1,%2,%3};"
        : "+f"(d.x), "+f"(d.y), "+f"(d.z), "+f"(d.w)
        : "r"(a[0]), "r"(a[1]), "r"(a[2]), "r"(a[3]), "r"(b[0]), "r"(b[1]));
}
#define LDSM4(r0, r1, r2, r3, addr) \
    asm volatile("ldmatrix.sync.aligned.m8n8.x4.shared.b16 {%0,%1,%2,%3}, [%4];" \
                 : "=r"(r0), "=r"(r1), "=r"(r2), "=r"(r3) : "r"(addr))

__device__ __forceinline__ uint32_t s2u(const void* p) {
    return (uint32_t)__cvta_generic_to_shared(p);
}
__device__ __forceinline__ void cpasync16(uint32_t dst, const void* src,
                                          uint32_t sz) {
    asm volatile("cp.async.cg.shared.global [%0], [%1], 16, %2;"
                 :: "r"(dst), "l"(src), "r"(sz));
}
#define CP_COMMIT() asm volatile("cp.async.commit_group;" ::: "memory")
#define CP_WAIT(n)  asm volatile("cp.async.wait_group %0;" :: "n"(n) : "memory")

// smem geometry (halfs): CTA tile 128x128, k-chunk 32 halfs, THREE stages
#define PITCH    40                      // halfs; 80B rows -> LDSM conflict-free
#define AT_H     (128 * PITCH)           // 5120 halfs per operand tile
#define STAGE_H  (2 * AT_H)              // 10240
#define STAGE_B  (STAGE_H * 2)           // 20480 bytes
#define SMEM_B   (3 * STAGE_B)           // 61440 bytes (2 CTAs/SM: 122880)

// ---------------- fp16 GEMM: C[m][n] = sum_k A[m][k]*B[n][k] ------------------
// CTA tile 128x128xK32, 256 threads (8 warps, 2x4), warp tile 64x32,
// 3-stage cp.async pipeline, ldmatrix fragment loads, 2 CTAs/SM
// (4 warps per SMSP for latency hiding).
template<bool DO_EXP>
__global__ void __launch_bounds__(256, 2)
gemm_mma(const __half* __restrict__ A, const __half* __restrict__ B,
         __half* __restrict__ C, int K, int MA, int NB, int ldc,
         long bA, long bB, long bC, float outscale)
{
    extern __shared__ __half sm[];
    const uint32_t smb = s2u(sm);
    const int tid = threadIdx.x;
    const int lane = tid & 31, wid = tid >> 5;
    const int wm = wid >> 2, wn = wid & 3;   // 2x4 warp grid
    const int lg = lane >> 2, lt = lane & 3;
    A += (long)blockIdx.z * bA;
    B += (long)blockIdx.z * bB;
    C += (long)blockIdx.z * bC;
    const int m0 = blockIdx.y * 128, n0 = blockIdx.x * 128;

    const int lrow = tid >> 2;          // 0..63
    const int lf4  = tid & 3;

    const __half* Abase = A + (long)(m0 + lrow) * K + lf4 * 8;
    const __half* Bbase = B + (long)(n0 + lrow) * K + lf4 * 8;
    const uint32_t dbase = lrow * (PITCH * 2) + lf4 * 16;

    // ldmatrix per-lane base offsets (bytes, within a stage)
    const uint32_t a_ld = ((wm * 64 + (lane & 15)) * PITCH + (lane >> 4) * 8) * 2;
    const uint32_t b_ld = AT_H * 2 +
        ((wn * 32 + (lane & 7) + ((lane >> 4) << 3)) * PITCH
         + ((lane >> 3) & 1) * 8) * 2;

    float4 acc[4][4];
#pragma unroll
    for (int i = 0; i < 4; i++)
#pragma unroll
        for (int j = 0; j < 4; j++) acc[i][j] = make_float4(0.f, 0.f, 0.f, 0.f);

    const int nk = K >> 5;

    auto issue = [&](int koff, uint32_t sa) {
#pragma unroll
        for (int it = 0; it < 2; it++) {
            const int row = lrow + it * 64;
            cpasync16(sa + dbase + it * (64 * PITCH * 2),
                      Abase + (long)(it * 64) * K + koff,
                      (m0 + row) < MA ? 16u : 0u);
            cpasync16(sa + AT_H * 2 + dbase + it * (64 * PITCH * 2),
                      Bbase + (long)(it * 64) * K + koff,
                      (n0 + row) < NB ? 16u : 0u);
        }
        CP_COMMIT();
    };

    issue(0, smb);
    if (nk > 1) issue(32, smb + STAGE_B);

    for (int ck = 0; ck < nk; ck++) {
        if (ck + 1 < nk) { CP_WAIT(1); } else { CP_WAIT(0); }
        __syncthreads();
        if (ck + 2 < nk) issue((ck + 2) * 32, smb + ((ck + 2) % 3) * STAGE_B);

        const uint32_t sbase = smb + (ck % 3) * STAGE_B;
#pragma unroll
        for (int ks = 0; ks < 2; ks++) {
            uint32_t af[4][4], bf[4][2];
#pragma unroll
            for (int mt = 0; mt < 4; mt++)
                LDSM4(af[mt][0], af[mt][1], af[mt][2], af[mt][3],
                      sbase + a_ld + (mt * 16 * PITCH + ks * 16) * 2);
#pragma unroll
            for (int ntp = 0; ntp < 2; ntp++)
                LDSM4(bf[2 * ntp][0], bf[2 * ntp][1],
                      bf[2 * ntp + 1][0], bf[2 * ntp + 1][1],
                      sbase + b_ld + (ntp * 16 * PITCH + ks * 16) * 2);
#pragma unroll
            for (int mt = 0; mt < 4; mt++)
#pragma unroll
                for (int nt = 0; nt < 4; nt++) mma16(acc[mt][nt], af[mt], bf[nt]);
        }
        __syncthreads();
    }

#pragma unroll
    for (int mt = 0; mt < 4; mt++) {
        const int r = m0 + wm * 64 + mt * 16 + lg;
#pragma unroll
        for (int nt = 0; nt < 4; nt++) {
            const int n = n0 + wn * 32 + nt * 8 + 2 * lt;
            float4 v = acc[mt][nt];
            if (DO_EXP) {
                v.x = __expf(v.x); v.y = __expf(v.y);
                v.z = __expf(v.z); v.w = __expf(v.w);
            }
            v.x *= outscale; v.y *= outscale; v.z *= outscale; v.w *= outscale;
            if (n < NB) {
                if (r < MA)
                    *(__half2*)(C + (long)r * ldc + n) = __floats2half2_rn(v.x, v.y);
                if (r + 8 < MA)
                    *(__half2*)(C + (long)(r + 8) * ldc + n) = __floats2half2_rn(v.z, v.w);
            }
        }
    }
}

// ---------------- conv 3x3 SAME via implicit GEMM (fp16 MMA, fp32 out) -------
__global__ void __launch_bounds__(256, 2)
conv_mma(const __half* __restrict__ attTe, const __half* __restrict__ attTq,
         const __half* __restrict__ wT, float* __restrict__ out)
{
    extern __shared__ __half sm[];
    const uint32_t smb = s2u(sm);
    const int tid = threadIdx.x;
    const int lane = tid & 31, wid = tid >> 5;
    const int wm = wid >> 2, wn = wid & 3;
    const int lg = lane >> 2, lt = lane & 3;
    const int z = blockIdx.z;
    const int b = z & 15, which = z >> 4;
    const __half* inT = (which ? attTq : attTe) + (long)b * N_PIX * CCH;
    const __half* wbase = wT + (long)which * 9 * CCH * CCH;
    const int m0 = blockIdx.y * 128;
    const int n0 = blockIdx.x * 128;

    const int lrow = tid >> 2;          // 0..63
    const int lf4  = tid & 3;
    const uint32_t dbase = lrow * (PITCH * 2) + lf4 * 16;

    const uint32_t a_ld = ((wm * 64 + (lane & 15)) * PITCH + (lane >> 4) * 8) * 2;
    const uint32_t b_ld = AT_H * 2 +
        ((wn * 32 + (lane & 7) + ((lane >> 4) << 3)) * PITCH
         + ((lane >> 3) & 1) * 8) * 2;

    int py_[2], px_[2];
    bool pv_[2];
#pragma unroll
    for (int it = 0; it < 2; it++) {
        int p = n0 + lrow + it * 64;
        py_[it] = p / 40; px_[it] = p % 40;
        pv_[it] = (p < N_PIX);
    }

    float4 acc[4][4];
#pragma unroll
    for (int i = 0; i < 4; i++)
#pragma unroll
        for (int j = 0; j < 4; j++) acc[i][j] = make_float4(0.f, 0.f, 0.f, 0.f);

    const int nk = 144;   // 9 kyx * 16 c-chunks

    auto issue = [&](int ck, uint32_t sa) {
        const int kyx = ck >> 4;
        const int cc = (ck & 15) * 32;
        const int dy = kyx / 3 - 1, dx = kyx % 3 - 1;
        const __half* wk = wbase + (long)kyx * (CCH * CCH) + cc
                           + (m0 + lrow) * CCH + lf4 * 8;
#pragma unroll
        for (int it = 0; it < 2; it++) {
            cpasync16(sa + dbase + it * (64 * PITCH * 2),
                      wk + it * (64 * CCH), 16u);
            int ys = py_[it] + dy, xs = px_[it] + dx;
            bool ok = pv_[it] && (unsigned)ys < 40u && (unsigned)xs < 40u;
            const __half* src = inT + (long)(ys * 40 + xs) * CCH + cc + lf4 * 8;
            cpasync16(sa + AT_H * 2 + dbase + it * (64 * PITCH * 2),
                      src, ok ? 16u : 0u);
        }
        CP_COMMIT();
    };

    issue(0, smb);
    issue(1, smb + STAGE_B);

    for (int ck = 0; ck < nk; ck++) {
        if (ck + 1 < nk) { CP_WAIT(1); } else { CP_WAIT(0); }
        __syncthreads();
        if (ck + 2 < nk) issue(ck + 2, smb + ((ck + 2) % 3) * STAGE_B);

        const uint32_t sbase = smb + (ck % 3) * STAGE_B;
#pragma unroll
        for (int ks = 0; ks < 2; ks++) {
            uint32_t af[4][4], bf[4][2];
#pragma unroll
            for (int mt = 0; mt < 4; mt++)
                LDSM4(af[mt][0], af[mt][1], af[mt][2], af[mt][3],
                      sbase + a_ld + (mt * 16 * PITCH + ks * 16) * 2);
#pragma unroll
            for (int ntp = 0; ntp < 2; ntp++)
                LDSM4(bf[2 * ntp][0], bf[2 * ntp][1],
                      bf[2 * ntp + 1][0], bf[2 * ntp + 1][1],
                      sbase + b_ld + (ntp * 16 * PITCH + ks * 16) * 2);
#pragma unroll
            for (int mt = 0; mt < 4; mt++)
#pragma unroll
                for (int nt = 0; nt < 4; nt++) mma16(acc[mt][nt], af[mt], bf[nt]);
        }
        __syncthreads();
    }

    float* obase = out + ((long)b * 2 * CCH + (long)which * CCH) * N_PIX;
#pragma unroll
    for (int mt = 0; mt < 4; mt++) {
        const int r = m0 + wm * 64 + mt * 16 + lg;
#pragma unroll
        for (int nt = 0; nt < 4; nt++) {
            const int n = n0 + wn * 32 + nt * 8 + 2 * lt;
            if (n < N_PIX) {
                float4 v = acc[mt][nt];
                *(float2*)(obase + (long)r * N_PIX + n) = make_float2(v.x, v.y);
                *(float2*)(obase + (long)(r + 8) * N_PIX + n) = make_float2(v.z, v.w);
            }
        }
    }
}

// ------------- dual input transpose [c][p] -> [p][c], float -> half ----------
__global__ void transpose_in(const float* __restrict__ s0, __half* __restrict__ d0,
                             const float* __restrict__ s1, __half* __restrict__ d1)
{
    __shared__ float t[32][33];
    const int z = blockIdx.z;
    const int b = z & 15, which = z >> 4;
    const long CN = (long)CCH * N_PIX;
    const float* src = (which ? s1 : s0) + (long)b * CN;
    __half* dst = (which ? d1 : d0) + (long)b * CN;
    const int x0 = blockIdx.x * 32, y0 = blockIdx.y * 32;
    const int tx = threadIdx.x, ty = threadIdx.y;
#pragma unroll
    for (int r = 0; r < 32; r += 8)
        t[ty + r][tx] = src[(long)(y0 + ty + r) * N_PIX + x0 + tx];
    __syncthreads();
#pragma unroll
    for (int r = 0; r < 32; r += 8)
        dst[(long)(x0 + ty + r) * CCH + y0 + tx] = __float2half(t[tx][ty + r]);
}

// ------- E transpose (half) + per-tile row/col partial sums (float) ----------
__global__ void transpose_es(const __half* __restrict__ E, __half* __restrict__ Et,
                             float* __restrict__ prow, float* __restrict__ pcol)
{
    __shared__ __half t[32][34];
    const long NN = (long)N_PIX * N_PIX;
    const int bz = blockIdx.z;
    const __half* src = E + bz * NN;
    __half* dst = Et + bz * NN;
    const int x0 = blockIdx.x * 32, y0 = blockIdx.y * 32;
    const int tx = threadIdx.x, ty = threadIdx.y;   // (32, 8)
#pragma unroll
    for (int r = 0; r < 32; r += 8)
        t[ty + r][tx] = src[(long)(y0 + ty + r) * N_PIX + x0 + tx];
    __syncthreads();

    if (ty == 0) {          // row sums (global row y0+tx)
        float s = 0.f;
#pragma unroll 8
        for (int j = 0; j < 32; j++) s += __half2float(t[tx][j]);
        prow[((bz * NTILE) + blockIdx.x) * N_PIX + y0 + tx] = s;
    } else if (ty == 1) {   // col sums (global col x0+tx)
        float s = 0.f;
#pragma unroll 8
        for (int i = 0; i < 32; i++) s += __half2float(t[i][tx]);
        pcol[((bz * NTILE) + blockIdx.y) * N_PIX + x0 + tx] = s;
    }
#pragma unroll
    for (int r = 0; r < 32; r += 8)
        dst[(long)(x0 + ty + r) * N_PIX + y0 + tx] = t[tx][ty + r];
}

// ------------- reduce partials over 50 tiles and invert ----------------------
__global__ void reduce_inv(const float* __restrict__ prow,
                           const float* __restrict__ pcol,
                           float* __restrict__ rsE, float* __restrict__ rsEt)
{
    int idx = blockIdx.x * 256 + threadIdx.x;   // b*N_PIX + n
    if (idx >= BATCH * N_PIX) return;
    const int b = idx / N_PIX, n = idx % N_PIX;
    const float* src = (blockIdx.y ? pcol : prow) + (long)b * NTILE * N_PIX + n;
    float s = 0.f;
#pragma unroll 10
    for (int tgt = 0; tgt < NTILE; tgt++) s += src[(long)tgt * N_PIX];
    (blockIdx.y ? rsEt : rsE)[idx] = 1.f / s;
}

// esc = exemplar*invColsum*4096; qsc = query*invRowsum*4096 (half out) --------
__global__ void scale_kernel(const float* __restrict__ ex,
                             const float* __restrict__ qu,
                             const float* __restrict__ invCs,
                             const float* __restrict__ invRs,
                             __half* __restrict__ e2, __half* __restrict__ q2)
{
    long idx = (long)blockIdx.x * 256 + threadIdx.x;
    if (idx >= (long)BATCH * CCH * N_PIX) return;
    int i = (int)(idx % N_PIX);
    int b = (int)(idx / ((long)CCH * N_PIX));
    e2[idx] = __float2half(ex[idx] * (invCs[b * N_PIX + i] * ESCALE));
    q2[idx] = __float2half(qu[idx] * (invRs[b * N_PIX + i] * ESCALE));
}

// ---------------- conv weights OIHW -> [which][kyx][o][c] (half) -------------
__global__ void wtrans_kernel(const float* __restrict__ w1,
                              const float* __restrict__ w2,
                              __half* __restrict__ wT)
{
    long idx = (long)blockIdx.x * 256 + threadIdx.x;
    const long per = 9L * CCH * CCH;
    if (idx >= 2 * per) return;
    int c = (int)(idx & (CCH - 1));
    long t = idx >> 9;
    int o = (int)(t & (CCH - 1));
    long t2 = t >> 9;
    int kyx = (int)(t2 % 9);
    int which = (int)(t2 / 9);
    const float* w = which ? w2 : w1;
    wT[idx] = __float2half(w[((long)o * CCH + c) * 9 + kyx]);
}

// ---------------- 1x1 weights: copy w_q, w_e to half --------------------------
__global__ void w1cvt_kernel(const float* __restrict__ wq,
                             const float* __restrict__ we,
                             __half* __restrict__ dst)
{
    int idx = blockIdx.x * 256 + threadIdx.x;
    if (idx >= 2 * CORR * CCH) return;
    const float* w = (idx < CORR * CCH) ? wq : we;
    dst[idx] = __float2half(w[idx < CORR * CCH ? idx : idx - CORR * CCH]);
}

// ---------------- launch ------------------------------------------------------
extern "C" void kernel_launch(void* const* d_in, const int* in_sizes, int n_in,
                              void* d_out, int out_size)
{
    const float* exemplar = (const float*)d_in[0];
    const float* query    = (const float*)d_in[1];
    const float* w_e      = (const float*)d_in[2];
    const float* w_q      = (const float*)d_in[3];
    const float* w_c1     = (const float*)d_in[4];
    const float* w_c2     = (const float*)d_in[5];
    float* out = (float*)d_out;

    __half *inTe, *inTq, *qcorr, *ecorr, *E, *Et, *esc, *qsc, *attTe, *attTq, *wT, *w1;
    float *prow, *pcol, *rsE, *rsEt;
    cudaGetSymbolAddress((void**)&inTe,  g_inTe);
    cudaGetSymbolAddress((void**)&inTq,  g_inTq);
    cudaGetSymbolAddress((void**)&qcorr, g_qcorr);
    cudaGetSymbolAddress((void**)&ecorr, g_ecorr);
    cudaGetSymbolAddress((void**)&E,     g_E);
    cudaGetSymbolAddress((void**)&Et,    g_Et);
    cudaGetSymbolAddress((void**)&prow,  g_prow);
    cudaGetSymbolAddress((void**)&pcol,  g_pcol);
    cudaGetSymbolAddress((void**)&rsE,   g_rsE);
    cudaGetSymbolAddress((void**)&rsEt,  g_rsEt);
    cudaGetSymbolAddress((void**)&esc,   g_esc);
    cudaGetSymbolAddress((void**)&qsc,   g_qsc);
    cudaGetSymbolAddress((void**)&attTe, g_attTe);
    cudaGetSymbolAddress((void**)&attTq, g_attTq);
    cudaGetSymbolAddress((void**)&wT,    g_wT);
    cudaGetSymbolAddress((void**)&w1,    g_w1);

    cudaFuncSetAttribute(gemm_mma<false>,
                         cudaFuncAttributeMaxDynamicSharedMemorySize, SMEM_B);
    cudaFuncSetAttribute(gemm_mma<true>,
                         cudaFuncAttributeMaxDynamicSharedMemorySize, SMEM_B);
    cudaFuncSetAttribute(conv_mma,
                         cudaFuncAttributeMaxDynamicSharedMemorySize, SMEM_B);

    const long NN = (long)N_PIX * N_PIX;
    const long CN = (long)CCH * N_PIX;
    const long NK = (long)N_PIX * CORR;

    // weight re-layouts (half)
    wtrans_kernel<<<(unsigned)((2L * 9 * CCH * CCH + 255) / 256), 256>>>(w_c1, w_c2, wT);
    w1cvt_kernel<<<(2 * CORR * CCH + 255) / 256, 256>>>(w_q, w_e, w1);

    // input transposes [c][p] -> [p][c] (half), both in one launch
    transpose_in<<<dim3(NTILE, 16, 32), dim3(32, 8)>>>(exemplar, inTe, query, inTq);

    // 1x1 projections: corr[p][o] = sum_c inT[p][c] * w[o][c]
    gemm_mma<false><<<dim3(2, 13, BATCH), 256, SMEM_B>>>(
        inTq, w1, qcorr, CCH, N_PIX, CORR, CORR, CN, 0L, NK, 1.0f);
    gemm_mma<false><<<dim3(2, 13, BATCH), 256, SMEM_B>>>(
        inTe, w1 + (long)CORR * CCH, ecorr, CCH, N_PIX, CORR, CORR, CN, 0L, NK, 1.0f);

    // E[n][m] = exp( sum_k ecorr[n][k] * qcorr[m][k] )
    gemm_mma<true><<<dim3(13, 13, BATCH), 256, SMEM_B>>>(
        ecorr, qcorr, E, CORR, N_PIX, N_PIX, N_PIX, NK, NK, NN, 1.0f);

    // Et = E^T, fused per-tile row/col partial sums
    transpose_es<<<dim3(NTILE, NTILE, BATCH), dim3(32, 8)>>>(E, Et, prow, pcol);
    reduce_inv<<<dim3((BATCH * N_PIX + 255) / 256, 2), 256>>>(prow, pcol, rsE, rsEt);

    // scaled inputs (softmax denominators folded into the small operand)
    scale_kernel<<<(unsigned)(((long)BATCH * CCH * N_PIX + 255) / 256), 256>>>(
        exemplar, query, rsEt, rsE, esc, qsc);

    // attention GEMMs (operand-swapped, outputs already transposed):
    //   attTq[j][c] = (sum_i E[j][i]  * esc[c][i]) / 4096
    //   attTe[j][c] = (sum_i Et[j][i] * qsc[c][i]) / 4096
    gemm_mma<false><<<dim3(4, 13, BATCH), 256, SMEM_B>>>(
        E, esc, attTq, N_PIX, N_PIX, CCH, CCH, NN, CN, CN, INV_ESCALE);
    gemm_mma<false><<<dim3(4, 13, BATCH), 256, SMEM_B>>>(
        Et, qsc, attTe, N_PIX, N_PIX, CCH, CCH, NN, CN, CN, INV_ESCALE);

    // 3x3 SAME convs into concatenated output
    conv_mma<<<dim3(13, 4, 2 * BATCH), 256, SMEM_B>>>(attTe, attTq, wT, out);
}

// round 14
// speedup vs baseline: 1.0143x; 1.0143x over previous
#include <cuda_runtime.h>
#include <cuda_fp16.h>
#include <cstdint>

#define N_PIX 1600
#define CCH   512
#define CORR  256
#define BATCH 16
#define NTILE 50    // N_PIX / 32

#define ESCALE 4096.0f
#define INV_ESCALE (1.0f / 4096.0f)

// ---------------- scratch (static __device__ arrays; allocation-free) -------
__device__ __half g_inTe  [BATCH * N_PIX * CCH];           // exemplar^T [p][c]
__device__ __half g_inTq  [BATCH * N_PIX * CCH];           // query^T    [p][c]
__device__ __half g_qcorr [BATCH * N_PIX * CORR];
__device__ __half g_ecorr [BATCH * N_PIX * CORR];
__device__ __half g_E     [(long)BATCH * N_PIX * N_PIX];   // exp(A)   82 MB
__device__ __half g_Et    [(long)BATCH * N_PIX * N_PIX];   // E^T      82 MB
__device__ float  g_prow  [BATCH * NTILE * N_PIX];
__device__ float  g_pcol  [BATCH * NTILE * N_PIX];
__device__ float  g_rsE   [BATCH * N_PIX];                 // 1/rowsum(E)
__device__ float  g_rsEt  [BATCH * N_PIX];                 // 1/colsum(E)
__device__ __half g_esc   [BATCH * CCH * N_PIX];           // exemplar*invColsum*4096
__device__ __half g_qsc   [BATCH * CCH * N_PIX];           // query*invRowsum*4096
__device__ __half g_attTe [BATCH * N_PIX * CCH];
__device__ __half g_attTq [BATCH * N_PIX * CCH];
__device__ __half g_wT    [2 * 9 * CCH * CCH];             // [which][kyx][o][c]
__device__ __half g_w1    [2 * CORR * CCH];

// ---------------- helpers -----------------------------------------------------
__device__ __forceinline__ void mma16(float4& d, const uint32_t a[4],
                                      const uint32_t b[2]) {
    asm volatile(
        "mma.sync.aligned.m16n8k16.row.col.f32.f16.f16.f32 "
        "{%0,%1,%2,%3}, {%4,%5,%6,%7}, {%8,%9}, {%0,%1,%2,%3};"
        : "+f"(d.x), "+f"(d.y), "+f"(d.z), "+f"(d.w)
        : "r"(a[0]), "r"(a[1]), "r"(a[2]), "r"(a[3]), "r"(b[0]), "r"(b[1]));
}
#define LDSM4(r0, r1, r2, r3, addr) \
    asm volatile("ldmatrix.sync.aligned.m8n8.x4.shared.b16 {%0,%1,%2,%3}, [%4];" \
                 : "=r"(r0), "=r"(r1), "=r"(r2), "=r"(r3) : "r"(addr))

__device__ __forceinline__ uint32_t s2u(const void* p) {
    return (uint32_t)__cvta_generic_to_shared(p);
}
__device__ __forceinline__ void cpasync16(uint32_t dst, const void* src,
                                          uint32_t sz) {
    asm volatile("cp.async.cg.shared.global [%0], [%1], 16, %2;"
                 :: "r"(dst), "l"(src), "r"(sz));
}
#define CP_COMMIT() asm volatile("cp.async.commit_group;" ::: "memory")
#define CP_WAIT(n)  asm volatile("cp.async.wait_group %0;" :: "n"(n) : "memory")

// smem geometry (halfs): CTA tile 128x128, k-chunk 32 halfs, THREE stages
#define PITCH    40                      // halfs; 80B rows -> LDSM conflict-free
#define AT_H     (128 * PITCH)           // 5120 halfs per operand tile
#define STAGE_H  (2 * AT_H)              // 10240
#define STAGE_B  (STAGE_H * 2)           // 20480 bytes
#define SMEM_B   (3 * STAGE_B)           // 61440 bytes (2 CTAs/SM: 122880)

// ---------------- fp16 GEMM: C[m][n] = sum_k A[m][k]*B[n][k] ------------------
// CTA tile 128x128xK32, 256 threads (8 warps, 2x4), warp tile 64x32,
// 3-stage cp.async pipeline, ONE barrier per chunk, ldmatrix loads, 2 CTAs/SM.
template<bool DO_EXP>
__global__ void __launch_bounds__(256, 2)
gemm_mma(const __half* __restrict__ A, const __half* __restrict__ B,
         __half* __restrict__ C, int K, int MA, int NB, int ldc,
         long bA, long bB, long bC, float outscale)
{
    extern __shared__ __half sm[];
    const uint32_t smb = s2u(sm);
    const int tid = threadIdx.x;
    const int lane = tid & 31, wid = tid >> 5;
    const int wm = wid >> 2, wn = wid & 3;   // 2x4 warp grid
    const int lg = lane >> 2, lt = lane & 3;
    A += (long)blockIdx.z * bA;
    B += (long)blockIdx.z * bB;
    C += (long)blockIdx.z * bC;
    const int m0 = blockIdx.y * 128, n0 = blockIdx.x * 128;

    const int lrow = tid >> 2;          // 0..63
    const int lf4  = tid & 3;

    const __half* Abase = A + (long)(m0 + lrow) * K + lf4 * 8;
    const __half* Bbase = B + (long)(n0 + lrow) * K + lf4 * 8;
    const uint32_t dbase = lrow * (PITCH * 2) + lf4 * 16;

    // ldmatrix per-lane base offsets (bytes, within a stage)
    const uint32_t a_ld = ((wm * 64 + (lane & 15)) * PITCH + (lane >> 4) * 8) * 2;
    const uint32_t b_ld = AT_H * 2 +
        ((wn * 32 + (lane & 7) + ((lane >> 4) << 3)) * PITCH
         + ((lane >> 3) & 1) * 8) * 2;

    float4 acc[4][4];
#pragma unroll
    for (int i = 0; i < 4; i++)
#pragma unroll
        for (int j = 0; j < 4; j++) acc[i][j] = make_float4(0.f, 0.f, 0.f, 0.f);

    const int nk = K >> 5;

    auto issue = [&](int koff, uint32_t sa) {
#pragma unroll
        for (int it = 0; it < 2; it++) {
            const int row = lrow + it * 64;
            cpasync16(sa + dbase + it * (64 * PITCH * 2),
                      Abase + (long)(it * 64) * K + koff,
                      (m0 + row) < MA ? 16u : 0u);
            cpasync16(sa + AT_H * 2 + dbase + it * (64 * PITCH * 2),
                      Bbase + (long)(it * 64) * K + koff,
                      (n0 + row) < NB ? 16u : 0u);
        }
        CP_COMMIT();
    };

    issue(0, smb);
    if (nk > 1) issue(32, smb + STAGE_B);

    for (int ck = 0; ck < nk; ck++) {
        if (ck + 1 < nk) { CP_WAIT(1); } else { CP_WAIT(0); }
        __syncthreads();
        if (ck + 2 < nk) issue((ck + 2) * 32, smb + ((ck + 2) % 3) * STAGE_B);

        const uint32_t sbase = smb + (ck % 3) * STAGE_B;
#pragma unroll
        for (int ks = 0; ks < 2; ks++) {
            uint32_t af[4][4], bf[4][2];
#pragma unroll
            for (int mt = 0; mt < 4; mt++)
                LDSM4(af[mt][0], af[mt][1], af[mt][2], af[mt][3],
                      sbase + a_ld + (mt * 16 * PITCH + ks * 16) * 2);
#pragma unroll
            for (int ntp = 0; ntp < 2; ntp++)
                LDSM4(bf[2 * ntp][0], bf[2 * ntp][1],
                      bf[2 * ntp + 1][0], bf[2 * ntp + 1][1],
                      sbase + b_ld + (ntp * 16 * PITCH + ks * 16) * 2);
#pragma unroll
            for (int mt = 0; mt < 4; mt++)
#pragma unroll
                for (int nt = 0; nt < 4; nt++) mma16(acc[mt][nt], af[mt], bf[nt]);
        }
    }

#pragma unroll
    for (int mt = 0; mt < 4; mt++) {
        const int r = m0 + wm * 64 + mt * 16 + lg;
#pragma unroll
        for (int nt = 0; nt < 4; nt++) {
            const int n = n0 + wn * 32 + nt * 8 + 2 * lt;
            float4 v = acc[mt][nt];
            if (DO_EXP) {
                v.x = __expf(v.x); v.y = __expf(v.y);
                v.z = __expf(v.z); v.w = __expf(v.w);
            }
            v.x *= outscale; v.y *= outscale; v.z *= outscale; v.w *= outscale;
            if (n < NB) {
                if (r < MA)
                    *(__half2*)(C + (long)r * ldc + n) = __floats2half2_rn(v.x, v.y);
                if (r + 8 < MA)
                    *(__half2*)(C + (long)(r + 8) * ldc + n) = __floats2half2_rn(v.z, v.w);
            }
        }
    }
}

// ---------------- conv 3x3 SAME via implicit GEMM (fp16 MMA, fp32 out) -------
__global__ void __launch_bounds__(256, 2)
conv_mma(const __half* __restrict__ attTe, const __half* __restrict__ attTq,
         const __half* __restrict__ wT, float* __restrict__ out)
{
    extern __shared__ __half sm[];
    const uint32_t smb = s2u(sm);
    const int tid = threadIdx.x;
    const int lane = tid & 31, wid = tid >> 5;
    const int wm = wid >> 2, wn = wid & 3;
    const int lg = lane >> 2, lt = lane & 3;
    const int z = blockIdx.z;
    const int b = z & 15, which = z >> 4;
    const __half* inT = (which ? attTq : attTe) + (long)b * N_PIX * CCH;
    const __half* wbase = wT + (long)which * 9 * CCH * CCH;
    const int m0 = blockIdx.y * 128;
    const int n0 = blockIdx.x * 128;

    const int lrow = tid >> 2;          // 0..63
    const int lf4  = tid & 3;
    const uint32_t dbase = lrow * (PITCH * 2) + lf4 * 16;

    const uint32_t a_ld = ((wm * 64 + (lane & 15)) * PITCH + (lane >> 4) * 8) * 2;
    const uint32_t b_ld = AT_H * 2 +
        ((wn * 32 + (lane & 7) + ((lane >> 4) << 3)) * PITCH
         + ((lane >> 3) & 1) * 8) * 2;

    int py_[2], px_[2];
    bool pv_[2];
#pragma unroll
    for (int it = 0; it < 2; it++) {
        int p = n0 + lrow + it * 64;
        py_[it] = p / 40; px_[it] = p % 40;
        pv_[it] = (p < N_PIX);
    }

    float4 acc[4][4];
#pragma unroll
    for (int i = 0; i < 4; i++)
#pragma unroll
        for (int j = 0; j < 4; j++) acc[i][j] = make_float4(0.f, 0.f, 0.f, 0.f);

    const int nk = 144;   // 9 kyx * 16 c-chunks

    auto issue = [&](int ck, uint32_t sa) {
        const int kyx = ck >> 4;
        const int cc = (ck & 15) * 32;
        const int dy = kyx / 3 - 1, dx = kyx % 3 - 1;
        const __half* wk = wbase + (long)kyx * (CCH * CCH) + cc
                           + (m0 + lrow) * CCH + lf4 * 8;
#pragma unroll
        for (int it = 0; it < 2; it++) {
            cpasync16(sa + dbase + it * (64 * PITCH * 2),
                      wk + it * (64 * CCH), 16u);
            int ys = py_[it] + dy, xs = px_[it] + dx;
            bool ok = pv_[it] && (unsigned)ys < 40u && (unsigned)xs < 40u;
            const __half* src = inT + (long)(ys * 40 + xs) * CCH + cc + lf4 * 8;
            cpasync16(sa + AT_H * 2 + dbase + it * (64 * PITCH * 2),
                      src, ok ? 16u : 0u);
        }
        CP_COMMIT();
    };

    issue(0, smb);
    issue(1, smb + STAGE_B);

    for (int ck = 0; ck < nk; ck++) {
        if (ck + 1 < nk) { CP_WAIT(1); } else { CP_WAIT(0); }
        __syncthreads();
        if (ck + 2 < nk) issue(ck + 2, smb + ((ck + 2) % 3) * STAGE_B);

        const uint32_t sbase = smb + (ck % 3) * STAGE_B;
#pragma unroll
        for (int ks = 0; ks < 2; ks++) {
            uint32_t af[4][4], bf[4][2];
#pragma unroll
            for (int mt = 0; mt < 4; mt++)
                LDSM4(af[mt][0], af[mt][1], af[mt][2], af[mt][3],
                      sbase + a_ld + (mt * 16 * PITCH + ks * 16) * 2);
#pragma unroll
            for (int ntp = 0; ntp < 2; ntp++)
                LDSM4(bf[2 * ntp][0], bf[2 * ntp][1],
                      bf[2 * ntp + 1][0], bf[2 * ntp + 1][1],
                      sbase + b_ld + (ntp * 16 * PITCH + ks * 16) * 2);
#pragma unroll
            for (int mt = 0; mt < 4; mt++)
#pragma unroll
                for (int nt = 0; nt < 4; nt++) mma16(acc[mt][nt], af[mt], bf[nt]);
        }
    }

    float* obase = out + ((long)b * 2 * CCH + (long)which * CCH) * N_PIX;
#pragma unroll
    for (int mt = 0; mt < 4; mt++) {
        const int r = m0 + wm * 64 + mt * 16 + lg;
#pragma unroll
        for (int nt = 0; nt < 4; nt++) {
            const int n = n0 + wn * 32 + nt * 8 + 2 * lt;
            if (n < N_PIX) {
                float4 v = acc[mt][nt];
                *(float2*)(obase + (long)r * N_PIX + n) = make_float2(v.x, v.y);
                *(float2*)(obase + (long)(r + 8) * N_PIX + n) = make_float2(v.z, v.w);
            }
        }
    }
}

// ------------- dual input transpose [c][p] -> [p][c], float -> half ----------
__global__ void transpose_in(const float* __restrict__ s0, __half* __restrict__ d0,
                             const float* __restrict__ s1, __half* __restrict__ d1)
{
    __shared__ float t[32][33];
    const int z = blockIdx.z;
    const int b = z & 15, which = z >> 4;
    const long CN = (long)CCH * N_PIX;
    const float* src = (which ? s1 : s0) + (long)b * CN;
    __half* dst = (which ? d1 : d0) + (long)b * CN;
    const int x0 = blockIdx.x * 32, y0 = blockIdx.y * 32;
    const int tx = threadIdx.x, ty = threadIdx.y;
#pragma unroll
    for (int r = 0; r < 32; r += 8)
        t[ty + r][tx] = src[(long)(y0 + ty + r) * N_PIX + x0 + tx];
    __syncthreads();
#pragma unroll
    for (int r = 0; r < 32; r += 8)
        dst[(long)(x0 + ty + r) * CCH + y0 + tx] = __float2half(t[tx][ty + r]);
}

// ------- E transpose (half) + per-tile row/col partial sums (float) ----------
__global__ void transpose_es(const __half* __restrict__ E, __half* __restrict__ Et,
                             float* __restrict__ prow, float* __restrict__ pcol)
{
    __shared__ __half t[32][34];
    const long NN = (long)N_PIX * N_PIX;
    const int bz = blockIdx.z;
    const __half* src = E + bz * NN;
    __half* dst = Et + bz * NN;
    const int x0 = blockIdx.x * 32, y0 = blockIdx.y * 32;
    const int tx = threadIdx.x, ty = threadIdx.y;   // (32, 8)
#pragma unroll
    for (int r = 0; r < 32; r += 8)
        t[ty + r][tx] = src[(long)(y0 + ty + r) * N_PIX + x0 + tx];
    __syncthreads();

    if (ty == 0) {          // row sums (global row y0+tx)
        float s = 0.f;
#pragma unroll 8
        for (int j = 0; j < 32; j++) s += __half2float(t[tx][j]);
        prow[((bz * NTILE) + blockIdx.x) * N_PIX + y0 + tx] = s;
    } else if (ty == 1) {   // col sums (global col x0+tx)
        float s = 0.f;
#pragma unroll 8
        for (int i = 0; i < 32; i++) s += __half2float(t[i][tx]);
        pcol[((bz * NTILE) + blockIdx.y) * N_PIX + x0 + tx] = s;
    }
#pragma unroll
    for (int r = 0; r < 32; r += 8)
        dst[(long)(x0 + ty + r) * N_PIX + y0 + tx] = t[tx][ty + r];
}

// ------------- reduce partials over 50 tiles and invert ----------------------
__global__ void reduce_inv(const float* __restrict__ prow,
                           const float* __restrict__ pcol,
                           float* __restrict__ rsE, float* __restrict__ rsEt)
{
    int idx = blockIdx.x * 256 + threadIdx.x;   // b*N_PIX + n
    if (idx >= BATCH * N_PIX) return;
    const int b = idx / N_PIX, n = idx % N_PIX;
    const float* src = (blockIdx.y ? pcol : prow) + (long)b * NTILE * N_PIX + n;
    float s = 0.f;
#pragma unroll 10
    for (int tgt = 0; tgt < NTILE; tgt++) s += src[(long)tgt * N_PIX];
    (blockIdx.y ? rsEt : rsE)[idx] = 1.f / s;
}

// esc = exemplar*invColsum*4096; qsc = query*invRowsum*4096 (half out) --------
__global__ void scale_kernel(const float* __restrict__ ex,
                             const float* __restrict__ qu,
                             const float* __restrict__ invCs,
                             const float* __restrict__ invRs,
                             __half* __restrict__ e2, __half* __restrict__ q2)
{
    long idx = (long)blockIdx.x * 256 + threadIdx.x;
    if (idx >= (long)BATCH * CCH * N_PIX) return;
    int i = (int)(idx % N_PIX);
    int b = (int)(idx / ((long)CCH * N_PIX));
    e2[idx] = __float2half(ex[idx] * (invCs[b * N_PIX + i] * ESCALE));
    q2[idx] = __float2half(qu[idx] * (invRs[b * N_PIX + i] * ESCALE));
}

// ---------------- conv weights OIHW -> [which][kyx][o][c] (half) -------------
__global__ void wtrans_kernel(const float* __restrict__ w1,
                              const float* __restrict__ w2,
                              __half* __restrict__ wT)
{
    long idx = (long)blockIdx.x * 256 + threadIdx.x;
    const long per = 9L * CCH * CCH;
    if (idx >= 2 * per) return;
    int c = (int)(idx & (CCH - 1));
    long t = idx >> 9;
    int o = (int)(t & (CCH - 1));
    long t2 = t >> 9;
    int kyx = (int)(t2 % 9);
    int which = (int)(t2 / 9);
    const float* w = which ? w2 : w1;
    wT[idx] = __float2half(w[((long)o * CCH + c) * 9 + kyx]);
}

// ---------------- 1x1 weights: copy w_q, w_e to half --------------------------
__global__ void w1cvt_kernel(const float* __restrict__ wq,
                             const float* __restrict__ we,
                             __half* __restrict__ dst)
{
    int idx = blockIdx.x * 256 + threadIdx.x;
    if (idx >= 2 * CORR * CCH) return;
    const float* w = (idx < CORR * CCH) ? wq : we;
    dst[idx] = __float2half(w[idx < CORR * CCH ? idx : idx - CORR * CCH]);
}

// ---------------- launch ------------------------------------------------------
extern "C" void kernel_launch(void* const* d_in, const int* in_sizes, int n_in,
                              void* d_out, int out_size)
{
    const float* exemplar = (const float*)d_in[0];
    const float* query    = (const float*)d_in[1];
    const float* w_e      = (const float*)d_in[2];
    const float* w_q      = (const float*)d_in[3];
    const float* w_c1     = (const float*)d_in[4];
    const float* w_c2     = (const float*)d_in[5];
    float* out = (float*)d_out;

    __half *inTe, *inTq, *qcorr, *ecorr, *E, *Et, *esc, *qsc, *attTe, *attTq, *wT, *w1;
    float *prow, *pcol, *rsE, *rsEt;
    cudaGetSymbolAddress((void**)&inTe,  g_inTe);
    cudaGetSymbolAddress((void**)&inTq,  g_inTq);
    cudaGetSymbolAddress((void**)&qcorr, g_qcorr);
    cudaGetSymbolAddress((void**)&ecorr, g_ecorr);
    cudaGetSymbolAddress((void**)&E,     g_E);
    cudaGetSymbolAddress((void**)&Et,    g_Et);
    cudaGetSymbolAddress((void**)&prow,  g_prow);
    cudaGetSymbolAddress((void**)&pcol,  g_pcol);
    cudaGetSymbolAddress((void**)&rsE,   g_rsE);
    cudaGetSymbolAddress((void**)&rsEt,  g_rsEt);
    cudaGetSymbolAddress((void**)&esc,   g_esc);
    cudaGetSymbolAddress((void**)&qsc,   g_qsc);
    cudaGetSymbolAddress((void**)&attTe, g_attTe);
    cudaGetSymbolAddress((void**)&attTq, g_attTq);
    cudaGetSymbolAddress((void**)&wT,    g_wT);
    cudaGetSymbolAddress((void**)&w1,    g_w1);

    cudaFuncSetAttribute(gemm_mma<false>,
                         cudaFuncAttributeMaxDynamicSharedMemorySize, SMEM_B);
    cudaFuncSetAttribute(gemm_mma<true>,
                         cudaFuncAttributeMaxDynamicSharedMemorySize, SMEM_B);
    cudaFuncSetAttribute(conv_mma,
                         cudaFuncAttributeMaxDynamicSharedMemorySize, SMEM_B);

    const long NN = (long)N_PIX * N_PIX;
    const long CN = (long)CCH * N_PIX;
    const long NK = (long)N_PIX * CORR;

    // weight re-layouts (half)
    wtrans_kernel<<<(unsigned)((2L * 9 * CCH * CCH + 255) / 256), 256>>>(w_c1, w_c2, wT);
    w1cvt_kernel<<<(2 * CORR * CCH + 255) / 256, 256>>>(w_q, w_e, w1);

    // input transposes [c][p] -> [p][c] (half), both in one launch
    transpose_in<<<dim3(NTILE, 16, 32), dim3(32, 8)>>>(exemplar, inTe, query, inTq);

    // 1x1 projections: corr[p][o] = sum_c inT[p][c] * w[o][c]
    gemm_mma<false><<<dim3(2, 13, BATCH), 256, SMEM_B>>>(
        inTq, w1, qcorr, CCH, N_PIX, CORR, CORR, CN, 0L, NK, 1.0f);
    gemm_mma<false><<<dim3(2, 13, BATCH), 256, SMEM_B>>>(
        inTe, w1 + (long)CORR * CCH, ecorr, CCH, N_PIX, CORR, CORR, CN, 0L, NK, 1.0f);

    // E[n][m] = exp( sum_k ecorr[n][k] * qcorr[m][k] )
    gemm_mma<true><<<dim3(13, 13, BATCH), 256, SMEM_B>>>(
        ecorr, qcorr, E, CORR, N_PIX, N_PIX, N_PIX, NK, NK, NN, 1.0f);

    // Et = E^T, fused per-tile row/col partial sums
    transpose_es<<<dim3(NTILE, NTILE, BATCH), dim3(32, 8)>>>(E, Et, prow, pcol);
    reduce_inv<<<dim3((BATCH * N_PIX + 255) / 256, 2), 256>>>(prow, pcol, rsE, rsEt);

    // scaled inputs (softmax denominators folded into the small operand)
    scale_kernel<<<(unsigned)(((long)BATCH * CCH * N_PIX + 255) / 256), 256>>>(
        exemplar, query, rsEt, rsE, esc, qsc);

    // attention GEMMs (operand-swapped, outputs already transposed):
    //   attTq[j][c] = (sum_i E[j][i]  * esc[c][i]) / 4096
    //   attTe[j][c] = (sum_i Et[j][i] * qsc[c][i]) / 4096
    gemm_mma<false><<<dim3(4, 13, BATCH), 256, SMEM_B>>>(
        E, esc, attTq, N_PIX, N_PIX, CCH, CCH, NN, CN, CN, INV_ESCALE);
    gemm_mma<false><<<dim3(4, 13, BATCH), 256, SMEM_B>>>(
        Et, qsc, attTe, N_PIX, N_PIX, CCH, CCH, NN, CN, CN, INV_ESCALE);

    // 3x3 SAME convs into concatenated output
    conv_mma<<<dim3(13, 4, 2 * BATCH), 256, SMEM_B>>>(attTe, attTq, wT, out);
}

// round 15
// speedup vs baseline: 1.0227x; 1.0083x over previous
#include <cuda_runtime.h>
#include <cuda_fp16.h>
#include <cstdint>

#define N_PIX 1600
#define CCH   512
#define CORR  256
#define BATCH 16
#define NTILE 50    // N_PIX / 32

#define ESCALE 4096.0f
#define INV_ESCALE (1.0f / 4096.0f)

// ---------------- scratch (static __device__ arrays; allocation-free) -------
__device__ __half g_inTe  [BATCH * N_PIX * CCH];           // exemplar^T [p][c]
__device__ __half g_inTq  [BATCH * N_PIX * CCH];           // query^T    [p][c]
__device__ __half g_qcorr [BATCH * N_PIX * CORR];
__device__ __half g_ecorr [BATCH * N_PIX * CORR];
__device__ __half g_E     [(long)BATCH * N_PIX * N_PIX];   // exp(A)   82 MB
__device__ __half g_Et    [(long)BATCH * N_PIX * N_PIX];   // E^T      82 MB
__device__ float  g_prow  [BATCH * NTILE * N_PIX];
__device__ float  g_pcol  [BATCH * NTILE * N_PIX];
__device__ float  g_rsE   [BATCH * N_PIX];                 // 1/rowsum(E)
__device__ float  g_rsEt  [BATCH * N_PIX];                 // 1/colsum(E)
__device__ __half g_esc   [BATCH * CCH * N_PIX];           // exemplar*invColsum*4096
__device__ __half g_qsc   [BATCH * CCH * N_PIX];           // query*invRowsum*4096
__device__ __half g_attTe [BATCH * N_PIX * CCH];
__device__ __half g_attTq [BATCH * N_PIX * CCH];
__device__ __half g_wT    [2 * 9 * CCH * CCH];             // [which][kyx][o][c]
__device__ __half g_w1    [2 * CORR * CCH];

// ---------------- helpers -----------------------------------------------------
__device__ __forceinline__ void mma16(float4& d, const uint32_t a[4],
                                      const uint32_t b[2]) {
    asm volatile(
        "mma.sync.aligned.m16n8k16.row.col.f32.f16.f16.f32 "
        "{%0,%1,%2,%3}, {%4,%5,%6,%7}, {%8,%9}, {%0,%1,%2,%3};"
        : "+f"(d.x), "+f"(d.y), "+f"(d.z), "+f"(d.w)
        : "r"(a[0]), "r"(a[1]), "r"(a[2]), "r"(a[3]), "r"(b[0]), "r"(b[1]));
}
#define LDSM4(r0, r1, r2, r3, addr) \
    asm volatile("ldmatrix.sync.aligned.m8n8.x4.shared.b16 {%0,%1,%2,%3}, [%4];" \
                 : "=r"(r0), "=r"(r1), "=r"(r2), "=r"(r3) : "r"(addr))

__device__ __forceinline__ uint32_t s2u(const void* p) {
    return (uint32_t)__cvta_generic_to_shared(p);
}
__device__ __forceinline__ void cpasync16(uint32_t dst, const void* src,
                                          uint32_t sz) {
    asm volatile("cp.async.cg.shared.global [%0], [%1], 16, %2;"
                 :: "r"(dst), "l"(src), "r"(sz));
}
#define CP_COMMIT() asm volatile("cp.async.commit_group;" ::: "memory")
#define CP_WAIT(n)  asm volatile("cp.async.wait_group %0;" :: "n"(n) : "memory")

// smem geometry (halfs): CTA tile 128x128, k-chunk 64 halfs, TWO stages
#define KCH      64
#define PITCH    72                      // halfs; 144B rows -> LDSM conflict-free
#define AT_H     (128 * PITCH)           // 9216 halfs per operand tile
#define STAGE_H  (2 * AT_H)              // 18432
#define STAGE_B  (STAGE_H * 2)           // 36864 bytes
#define SMEM_B   (2 * STAGE_B)           // 73728 bytes (2 CTAs/SM: 147456)

// ---------------- fp16 GEMM: C[m][n] = sum_k A[m][k]*B[n][k] ------------------
// CTA tile 128x128xK64, 128 threads (4 warps 2x2), warp tile 64x64,
// 2-stage cp.async, ONE barrier per chunk, ldmatrix loads, 2 CTAs/SM.
template<bool DO_EXP>
__global__ void __launch_bounds__(128, 2)
gemm_mma(const __half* __restrict__ A, const __half* __restrict__ B,
         __half* __restrict__ C, int K, int MA, int NB, int ldc,
         long bA, long bB, long bC, float outscale)
{
    extern __shared__ __half sm[];
    const uint32_t smb = s2u(sm);
    const int tid = threadIdx.x;
    const int lane = tid & 31, wid = tid >> 5;
    const int wm = wid >> 1, wn = wid & 1;
    const int lg = lane >> 2, lt = lane & 3;
    A += (long)blockIdx.z * bA;
    B += (long)blockIdx.z * bB;
    C += (long)blockIdx.z * bC;
    const int m0 = blockIdx.y * 128, n0 = blockIdx.x * 128;

    const int lrow = tid >> 3;          // 0..15
    const int lf8  = tid & 7;           // 16B chunk within 128B row

    const __half* Abase = A + (long)(m0 + lrow) * K + lf8 * 8;
    const __half* Bbase = B + (long)(n0 + lrow) * K + lf8 * 8;
    const uint32_t dbase = lrow * (PITCH * 2) + lf8 * 16;

    // ldmatrix per-lane base offsets (bytes, within a stage)
    const uint32_t a_ld = ((wm * 64 + (lane & 15)) * PITCH + (lane >> 4) * 8) * 2;
    const uint32_t b_ld = AT_H * 2 +
        ((wn * 64 + (lane & 7) + ((lane >> 4) << 3)) * PITCH
         + ((lane >> 3) & 1) * 8) * 2;

    float4 acc[4][8];
#pragma unroll
    for (int i = 0; i < 4; i++)
#pragma unroll
        for (int j = 0; j < 8; j++) acc[i][j] = make_float4(0.f, 0.f, 0.f, 0.f);

    const int nk = K / KCH;

    auto issue = [&](int koff, uint32_t sa) {
#pragma unroll
        for (int it = 0; it < 8; it++) {
            const int row = lrow + it * 16;
            cpasync16(sa + dbase + it * (16 * PITCH * 2),
                      Abase + (long)(it * 16) * K + koff,
                      (m0 + row) < MA ? 16u : 0u);
            cpasync16(sa + AT_H * 2 + dbase + it * (16 * PITCH * 2),
                      Bbase + (long)(it * 16) * K + koff,
                      (n0 + row) < NB ? 16u : 0u);
        }
        CP_COMMIT();
    };

    issue(0, smb);

    for (int ck = 0; ck < nk; ck++) {
        CP_WAIT(0);
        __syncthreads();
        if (ck + 1 < nk) issue((ck + 1) * KCH, smb + ((ck + 1) & 1) * STAGE_B);

        const uint32_t sbase = smb + (ck & 1) * STAGE_B;
#pragma unroll
        for (int ks = 0; ks < 4; ks++) {
            uint32_t af[4][4], bf[8][2];
#pragma unroll
            for (int mt = 0; mt < 4; mt++)
                LDSM4(af[mt][0], af[mt][1], af[mt][2], af[mt][3],
                      sbase + a_ld + (mt * 16 * PITCH + ks * 16) * 2);
#pragma unroll
            for (int ntp = 0; ntp < 4; ntp++)
                LDSM4(bf[2 * ntp][0], bf[2 * ntp][1],
                      bf[2 * ntp + 1][0], bf[2 * ntp + 1][1],
                      sbase + b_ld + (ntp * 16 * PITCH + ks * 16) * 2);
#pragma unroll
            for (int mt = 0; mt < 4; mt++)
#pragma unroll
                for (int nt = 0; nt < 8; nt++) mma16(acc[mt][nt], af[mt], bf[nt]);
        }
    }

#pragma unroll
    for (int mt = 0; mt < 4; mt++) {
        const int r = m0 + wm * 64 + mt * 16 + lg;
#pragma unroll
        for (int nt = 0; nt < 8; nt++) {
            const int n = n0 + wn * 64 + nt * 8 + 2 * lt;
            float4 v = acc[mt][nt];
            if (DO_EXP) {
                v.x = __expf(v.x); v.y = __expf(v.y);
                v.z = __expf(v.z); v.w = __expf(v.w);
            }
            v.x *= outscale; v.y *= outscale; v.z *= outscale; v.w *= outscale;
            if (n < NB) {
                if (r < MA)
                    *(__half2*)(C + (long)r * ldc + n) = __floats2half2_rn(v.x, v.y);
                if (r + 8 < MA)
                    *(__half2*)(C + (long)(r + 8) * ldc + n) = __floats2half2_rn(v.z, v.w);
            }
        }
    }
}

// ---------------- conv 3x3 SAME via implicit GEMM (fp16 MMA, fp32 out) -------
// k-chunk = 64 channels; nk = 9 kyx * 8 c-chunks = 72
__global__ void __launch_bounds__(128, 2)
conv_mma(const __half* __restrict__ attTe, const __half* __restrict__ attTq,
         const __half* __restrict__ wT, float* __restrict__ out)
{
    extern __shared__ __half sm[];
    const uint32_t smb = s2u(sm);
    const int tid = threadIdx.x;
    const int lane = tid & 31, wid = tid >> 5;
    const int wm = wid >> 1, wn = wid & 1;
    const int lg = lane >> 2, lt = lane & 3;
    const int z = blockIdx.z;
    const int b = z & 15, which = z >> 4;
    const __half* inT = (which ? attTq : attTe) + (long)b * N_PIX * CCH;
    const __half* wbase = wT + (long)which * 9 * CCH * CCH;
    const int m0 = blockIdx.y * 128;
    const int n0 = blockIdx.x * 128;

    const int lrow = tid >> 3;
    const int lf8  = tid & 7;
    const uint32_t dbase = lrow * (PITCH * 2) + lf8 * 16;

    const uint32_t a_ld = ((wm * 64 + (lane & 15)) * PITCH + (lane >> 4) * 8) * 2;
    const uint32_t b_ld = AT_H * 2 +
        ((wn * 64 + (lane & 7) + ((lane >> 4) << 3)) * PITCH
         + ((lane >> 3) & 1) * 8) * 2;

    int py_[8], px_[8];
    bool pv_[8];
#pragma unroll
    for (int it = 0; it < 8; it++) {
        int p = n0 + lrow + it * 16;
        py_[it] = p / 40; px_[it] = p % 40;
        pv_[it] = (p < N_PIX);
    }

    float4 acc[4][8];
#pragma unroll
    for (int i = 0; i < 4; i++)
#pragma unroll
        for (int j = 0; j < 8; j++) acc[i][j] = make_float4(0.f, 0.f, 0.f, 0.f);

    const int nk = 72;   // 9 kyx * 8 c-chunks of 64

    auto issue = [&](int ck, uint32_t sa) {
        const int kyx = ck >> 3;
        const int cc = (ck & 7) * KCH;
        const int dy = kyx / 3 - 1, dx = kyx % 3 - 1;
        const __half* wk = wbase + (long)kyx * (CCH * CCH) + cc
                           + (m0 + lrow) * CCH + lf8 * 8;
#pragma unroll
        for (int it = 0; it < 8; it++) {
            cpasync16(sa + dbase + it * (16 * PITCH * 2),
                      wk + it * (16 * CCH), 16u);
            int ys = py_[it] + dy, xs = px_[it] + dx;
            bool ok = pv_[it] && (unsigned)ys < 40u && (unsigned)xs < 40u;
            const __half* src = inT + (long)(ys * 40 + xs) * CCH + cc + lf8 * 8;
            cpasync16(sa + AT_H * 2 + dbase + it * (16 * PITCH * 2),
                      src, ok ? 16u : 0u);
        }
        CP_COMMIT();
    };

    issue(0, smb);

    for (int ck = 0; ck < nk; ck++) {
        CP_WAIT(0);
        __syncthreads();
        if (ck + 1 < nk) issue(ck + 1, smb + ((ck + 1) & 1) * STAGE_B);

        const uint32_t sbase = smb + (ck & 1) * STAGE_B;
#pragma unroll
        for (int ks = 0; ks < 4; ks++) {
            uint32_t af[4][4], bf[8][2];
#pragma unroll
            for (int mt = 0; mt < 4; mt++)
                LDSM4(af[mt][0], af[mt][1], af[mt][2], af[mt][3],
                      sbase + a_ld + (mt * 16 * PITCH + ks * 16) * 2);
#pragma unroll
            for (int ntp = 0; ntp < 4; ntp++)
                LDSM4(bf[2 * ntp][0], bf[2 * ntp][1],
                      bf[2 * ntp + 1][0], bf[2 * ntp + 1][1],
                      sbase + b_ld + (ntp * 16 * PITCH + ks * 16) * 2);
#pragma unroll
            for (int mt = 0; mt < 4; mt++)
#pragma unroll
                for (int nt = 0; nt < 8; nt++) mma16(acc[mt][nt], af[mt], bf[nt]);
        }
    }

    float* obase = out + ((long)b * 2 * CCH + (long)which * CCH) * N_PIX;
#pragma unroll
    for (int mt = 0; mt < 4; mt++) {
        const int r = m0 + wm * 64 + mt * 16 + lg;
#pragma unroll
        for (int nt = 0; nt < 8; nt++) {
            const int n = n0 + wn * 64 + nt * 8 + 2 * lt;
            if (n < N_PIX) {
                float4 v = acc[mt][nt];
                *(float2*)(obase + (long)r * N_PIX + n) = make_float2(v.x, v.y);
                *(float2*)(obase + (long)(r + 8) * N_PIX + n) = make_float2(v.z, v.w);
            }
        }
    }
}

// ------------- dual input transpose [c][p] -> [p][c], float -> half ----------
__global__ void transpose_in(const float* __restrict__ s0, __half* __restrict__ d0,
                             const float* __restrict__ s1, __half* __restrict__ d1)
{
    __shared__ float t[32][33];
    const int z = blockIdx.z;
    const int b = z & 15, which = z >> 4;
    const long CN = (long)CCH * N_PIX;
    const float* src = (which ? s1 : s0) + (long)b * CN;
    __half* dst = (which ? d1 : d0) + (long)b * CN;
    const int x0 = blockIdx.x * 32, y0 = blockIdx.y * 32;
    const int tx = threadIdx.x, ty = threadIdx.y;
#pragma unroll
    for (int r = 0; r < 32; r += 8)
        t[ty + r][tx] = src[(long)(y0 + ty + r) * N_PIX + x0 + tx];
    __syncthreads();
#pragma unroll
    for (int r = 0; r < 32; r += 8)
        dst[(long)(x0 + ty + r) * CCH + y0 + tx] = __float2half(t[tx][ty + r]);
}

// ------- E transpose (half) + per-tile row/col partial sums (float) ----------
__global__ void transpose_es(const __half* __restrict__ E, __half* __restrict__ Et,
                             float* __restrict__ prow, float* __restrict__ pcol)
{
    __shared__ __half t[32][34];
    const long NN = (long)N_PIX * N_PIX;
    const int bz = blockIdx.z;
    const __half* src = E + bz * NN;
    __half* dst = Et + bz * NN;
    const int x0 = blockIdx.x * 32, y0 = blockIdx.y * 32;
    const int tx = threadIdx.x, ty = threadIdx.y;   // (32, 8)
#pragma unroll
    for (int r = 0; r < 32; r += 8)
        t[ty + r][tx] = src[(long)(y0 + ty + r) * N_PIX + x0 + tx];
    __syncthreads();

    if (ty == 0) {          // row sums (global row y0+tx)
        float s = 0.f;
#pragma unroll 8
        for (int j = 0; j < 32; j++) s += __half2float(t[tx][j]);
        prow[((bz * NTILE) + blockIdx.x) * N_PIX + y0 + tx] = s;
    } else if (ty == 1) {   // col sums (global col x0+tx)
        float s = 0.f;
#pragma unroll 8
        for (int i = 0; i < 32; i++) s += __half2float(t[i][tx]);
        pcol[((bz * NTILE) + blockIdx.y) * N_PIX + x0 + tx] = s;
    }
#pragma unroll
    for (int r = 0; r < 32; r += 8)
        dst[(long)(x0 + ty + r) * N_PIX + y0 + tx] = t[tx][ty + r];
}

// ------------- reduce partials over 50 tiles and invert ----------------------
__global__ void reduce_inv(const float* __restrict__ prow,
                           const float* __restrict__ pcol,
                           float* __restrict__ rsE, float* __restrict__ rsEt)
{
    int idx = blockIdx.x * 256 + threadIdx.x;   // b*N_PIX + n
    if (idx >= BATCH * N_PIX) return;
    const int b = idx / N_PIX, n = idx % N_PIX;
    const float* src = (blockIdx.y ? pcol : prow) + (long)b * NTILE * N_PIX + n;
    float s = 0.f;
#pragma unroll 10
    for (int tgt = 0; tgt < NTILE; tgt++) s += src[(long)tgt * N_PIX];
    (blockIdx.y ? rsEt : rsE)[idx] = 1.f / s;
}

// esc = exemplar*invColsum*4096; qsc = query*invRowsum*4096 (half out) --------
__global__ void scale_kernel(const float* __restrict__ ex,
                             const float* __restrict__ qu,
                             const float* __restrict__ invCs,
                             const float* __restrict__ invRs,
                             __half* __restrict__ e2, __half* __restrict__ q2)
{
    long idx = (long)blockIdx.x * 256 + threadIdx.x;
    if (idx >= (long)BATCH * CCH * N_PIX) return;
    int i = (int)(idx % N_PIX);
    int b = (int)(idx / ((long)CCH * N_PIX));
    e2[idx] = __float2half(ex[idx] * (invCs[b * N_PIX + i] * ESCALE));
    q2[idx] = __float2half(qu[idx] * (invRs[b * N_PIX + i] * ESCALE));
}

// ---------------- conv weights OIHW -> [which][kyx][o][c] (half) -------------
__global__ void wtrans_kernel(const float* __restrict__ w1,
                              const float* __restrict__ w2,
                              __half* __restrict__ wT)
{
    long idx = (long)blockIdx.x * 256 + threadIdx.x;
    const long per = 9L * CCH * CCH;
    if (idx >= 2 * per) return;
    int c = (int)(idx & (CCH - 1));
    long t = idx >> 9;
    int o = (int)(t & (CCH - 1));
    long t2 = t >> 9;
    int kyx = (int)(t2 % 9);
    int which = (int)(t2 / 9);
    const float* w = which ? w2 : w1;
    wT[idx] = __float2half(w[((long)o * CCH + c) * 9 + kyx]);
}

// ---------------- 1x1 weights: copy w_q, w_e to half --------------------------
__global__ void w1cvt_kernel(const float* __restrict__ wq,
                             const float* __restrict__ we,
                             __half* __restrict__ dst)
{
    int idx = blockIdx.x * 256 + threadIdx.x;
    if (idx >= 2 * CORR * CCH) return;
    const float* w = (idx < CORR * CCH) ? wq : we;
    dst[idx] = __float2half(w[idx < CORR * CCH ? idx : idx - CORR * CCH]);
}

// ---------------- launch ------------------------------------------------------
extern "C" void kernel_launch(void* const* d_in, const int* in_sizes, int n_in,
                              void* d_out, int out_size)
{
    const float* exemplar = (const float*)d_in[0];
    const float* query    = (const float*)d_in[1];
    const float* w_e      = (const float*)d_in[2];
    const float* w_q      = (const float*)d_in[3];
    const float* w_c1     = (const float*)d_in[4];
    const float* w_c2     = (const float*)d_in[5];
    float* out = (float*)d_out;

    __half *inTe, *inTq, *qcorr, *ecorr, *E, *Et, *esc, *qsc, *attTe, *attTq, *wT, *w1;
    float *prow, *pcol, *rsE, *rsEt;
    cudaGetSymbolAddress((void**)&inTe,  g_inTe);
    cudaGetSymbolAddress((void**)&inTq,  g_inTq);
    cudaGetSymbolAddress((void**)&qcorr, g_qcorr);
    cudaGetSymbolAddress((void**)&ecorr, g_ecorr);
    cudaGetSymbolAddress((void**)&E,     g_E);
    cudaGetSymbolAddress((void**)&Et,    g_Et);
    cudaGetSymbolAddress((void**)&prow,  g_prow);
    cudaGetSymbolAddress((void**)&pcol,  g_pcol);
    cudaGetSymbolAddress((void**)&rsE,   g_rsE);
    cudaGetSymbolAddress((void**)&rsEt,  g_rsEt);
    cudaGetSymbolAddress((void**)&esc,   g_esc);
    cudaGetSymbolAddress((void**)&qsc,   g_qsc);
    cudaGetSymbolAddress((void**)&attTe, g_attTe);
    cudaGetSymbolAddress((void**)&attTq, g_attTq);
    cudaGetSymbolAddress((void**)&wT,    g_wT);
    cudaGetSymbolAddress((void**)&w1,    g_w1);

    cudaFuncSetAttribute(gemm_mma<false>,
                         cudaFuncAttributeMaxDynamicSharedMemorySize, SMEM_B);
    cudaFuncSetAttribute(gemm_mma<true>,
                         cudaFuncAttributeMaxDynamicSharedMemorySize, SMEM_B);
    cudaFuncSetAttribute(conv_mma,
                         cudaFuncAttributeMaxDynamicSharedMemorySize, SMEM_B);

    const long NN = (long)N_PIX * N_PIX;
    const long CN = (long)CCH * N_PIX;
    const long NK = (long)N_PIX * CORR;

    // weight re-layouts (half)
    wtrans_kernel<<<(unsigned)((2L * 9 * CCH * CCH + 255) / 256), 256>>>(w_c1, w_c2, wT);
    w1cvt_kernel<<<(2 * CORR * CCH + 255) / 256, 256>>>(w_q, w_e, w1);

    // input transposes [c][p] -> [p][c] (half), both in one launch
    transpose_in<<<dim3(NTILE, 16, 32), dim3(32, 8)>>>(exemplar, inTe, query, inTq);

    // 1x1 projections: corr[p][o] = sum_c inT[p][c] * w[o][c]
    gemm_mma<false><<<dim3(2, 13, BATCH), 128, SMEM_B>>>(
        inTq, w1, qcorr, CCH, N_PIX, CORR, CORR, CN, 0L, NK, 1.0f);
    gemm_mma<false><<<dim3(2, 13, BATCH), 128, SMEM_B>>>(
        inTe, w1 + (long)CORR * CCH, ecorr, CCH, N_PIX, CORR, CORR, CN, 0L, NK, 1.0f);

    // E[n][m] = exp( sum_k ecorr[n][k] * qcorr[m][k] )
    gemm_mma<true><<<dim3(13, 13, BATCH), 128, SMEM_B>>>(
        ecorr, qcorr, E, CORR, N_PIX, N_PIX, N_PIX, NK, NK, NN, 1.0f);

    // Et = E^T, fused per-tile row/col partial sums
    transpose_es<<<dim3(NTILE, NTILE, BATCH), dim3(32, 8)>>>(E, Et, prow, pcol);
    reduce_inv<<<dim3((BATCH * N_PIX + 255) / 256, 2), 256>>>(prow, pcol, rsE, rsEt);

    // scaled inputs (softmax denominators folded into the small operand)
    scale_kernel<<<(unsigned)(((long)BATCH * CCH * N_PIX + 255) / 256), 256>>>(
        exemplar, query, rsEt, rsE, esc, qsc);

    // attention GEMMs (operand-swapped, outputs already transposed):
    //   attTq[j][c] = (sum_i E[j][i]  * esc[c][i]) / 4096
    //   attTe[j][c] = (sum_i Et[j][i] * qsc[c][i]) / 4096
    gemm_mma<false><<<dim3(4, 13, BATCH), 128, SMEM_B>>>(
        E, esc, attTq, N_PIX, N_PIX, CCH, CCH, NN, CN, CN, INV_ESCALE);
    gemm_mma<false><<<dim3(4, 13, BATCH), 128, SMEM_B>>>(
        Et, qsc, attTe, N_PIX, N_PIX, CCH, CCH, NN, CN, CN, INV_ESCALE);

    // 3x3 SAME convs into concatenated output
    conv_mma<<<dim3(13, 4, 2 * BATCH), 128, SMEM_B>>>(attTe, attTq, wT, out);
}

// round 16
// speedup vs baseline: 1.1651x; 1.1392x over previous
#include <cuda_runtime.h>
#include <cuda_fp16.h>
#include <cstdint>

#define N_PIX 1600
#define CCH   512
#define CORR  256
#define BATCH 16
#define NTILE 50    // N_PIX / 32

#define ESCALE 4096.0f
#define INV_ESCALE (1.0f / 4096.0f)

// ---------------- scratch (static __device__ arrays; allocation-free) -------
__device__ __half g_inTe  [BATCH * N_PIX * CCH];           // exemplar^T [p][c]
__device__ __half g_inTq  [BATCH * N_PIX * CCH];           // query^T    [p][c]
__device__ __half g_qcorr [BATCH * N_PIX * CORR];
__device__ __half g_ecorr [BATCH * N_PIX * CORR];
__device__ __half g_E     [(long)BATCH * N_PIX * N_PIX];   // exp(A)   82 MB
__device__ __half g_Et    [(long)BATCH * N_PIX * N_PIX];   // E^T      82 MB
__device__ float  g_prow  [BATCH * NTILE * N_PIX];
__device__ float  g_pcol  [BATCH * NTILE * N_PIX];
__device__ float  g_rsE   [BATCH * N_PIX];                 // 1/rowsum(E)
__device__ float  g_rsEt  [BATCH * N_PIX];                 // 1/colsum(E)
__device__ __half g_esc   [BATCH * CCH * N_PIX];           // exemplar*invColsum*4096
__device__ __half g_qsc   [BATCH * CCH * N_PIX];           // query*invRowsum*4096
__device__ __half g_attTe [BATCH * N_PIX * CCH];
__device__ __half g_attTq [BATCH * N_PIX * CCH];
__device__ __half g_wT    [2 * 9 * CCH * CCH];             // [which][kyx][o][c]
__device__ __half g_w1    [2 * CORR * CCH];

// ---------------- helpers -----------------------------------------------------
__device__ __forceinline__ void mma16(float4& d, const uint32_t a[4],
                                      const uint32_t b[2]) {
    asm volatile(
        "mma.sync.aligned.m16n8k16.row.col.f32.f16.f16.f32 "
        "{%0,%1,%2,%3}, {%4,%5,%6,%7}, {%8,%9}, {%0,%1,%2,%3};"
        : "+f"(d.x), "+f"(d.y), "+f"(d.z), "+f"(d.w)
        : "r"(a[0]), "r"(a[1]), "r"(a[2]), "r"(a[3]), "r"(b[0]), "r"(b[1]));
}
#define LDSM4(r0, r1, r2, r3, addr) \
    asm volatile("ldmatrix.sync.aligned.m8n8.x4.shared.b16 {%0,%1,%2,%3}, [%4];" \
                 : "=r"(r0), "=r"(r1), "=r"(r2), "=r"(r3) : "r"(addr))

__device__ __forceinline__ uint32_t s2u(const void* p) {
    return (uint32_t)__cvta_generic_to_shared(p);
}
__device__ __forceinline__ void cpasync16(uint32_t dst, const void* src,
                                          uint32_t sz) {
    asm volatile("cp.async.cg.shared.global [%0], [%1], 16, %2;"
                 :: "r"(dst), "l"(src), "r"(sz));
}
#define CP_COMMIT() asm volatile("cp.async.commit_group;" ::: "memory")
#define CP_WAIT(n)  asm volatile("cp.async.wait_group %0;" :: "n"(n) : "memory")

// smem geometry (halfs): CTA tile 128x128, k-chunk 32 halfs, THREE stages
#define PITCH    40                      // halfs; 80B rows -> LDSM conflict-free
#define AT_H     (128 * PITCH)           // 5120 halfs per operand tile
#define STAGE_H  (2 * AT_H)              // 10240
#define STAGE_B  (STAGE_H * 2)           // 20480 bytes
#define SMEM_B   (3 * STAGE_B)           // 61440 bytes

// ---------------- fp16 GEMM: C[m][n] = sum_k A[m][k]*B[n][k] ------------------
// CTA tile 128x128xK32, 128 threads (4 warps 2x2), warp tile 64x64,
// 3-stage cp.async pipeline, ldmatrix fragment loads, 2 CTAs/SM.  (R10 best)
template<bool DO_EXP>
__global__ void __launch_bounds__(128, 2)
gemm_mma(const __half* __restrict__ A, const __half* __restrict__ B,
         __half* __restrict__ C, int K, int MA, int NB, int ldc,
         long bA, long bB, long bC, float outscale)
{
    extern __shared__ __half sm[];
    const uint32_t smb = s2u(sm);
    const int tid = threadIdx.x;
    const int lane = tid & 31, wid = tid >> 5;
    const int wm = wid >> 1, wn = wid & 1;
    const int lg = lane >> 2, lt = lane & 3;
    A += (long)blockIdx.z * bA;
    B += (long)blockIdx.z * bB;
    C += (long)blockIdx.z * bC;
    const int m0 = blockIdx.y * 128, n0 = blockIdx.x * 128;

    const int lrow = tid >> 2;          // 0..31
    const int lf4  = tid & 3;

    const __half* Abase = A + (long)(m0 + lrow) * K + lf4 * 8;
    const __half* Bbase = B + (long)(n0 + lrow) * K + lf4 * 8;
    const uint32_t dbase = lrow * (PITCH * 2) + lf4 * 16;

    const uint32_t a_ld = ((wm * 64 + (lane & 15)) * PITCH + (lane >> 4) * 8) * 2;
    const uint32_t b_ld = AT_H * 2 +
        ((wn * 64 + (lane & 7) + ((lane >> 4) << 3)) * PITCH
         + ((lane >> 3) & 1) * 8) * 2;

    float4 acc[4][8];
#pragma unroll
    for (int i = 0; i < 4; i++)
#pragma unroll
        for (int j = 0; j < 8; j++) acc[i][j] = make_float4(0.f, 0.f, 0.f, 0.f);

    const int nk = K >> 5;

    auto issue = [&](int koff, uint32_t sa) {
#pragma unroll
        for (int it = 0; it < 4; it++) {
            const int row = lrow + it * 32;
            cpasync16(sa + dbase + it * (32 * PITCH * 2),
                      Abase + (long)(it * 32) * K + koff,
                      (m0 + row) < MA ? 16u : 0u);
            cpasync16(sa + AT_H * 2 + dbase + it * (32 * PITCH * 2),
                      Bbase + (long)(it * 32) * K + koff,
                      (n0 + row) < NB ? 16u : 0u);
        }
        CP_COMMIT();
    };

    issue(0, smb);
    if (nk > 1) issue(32, smb + STAGE_B);

    for (int ck = 0; ck < nk; ck++) {
        if (ck + 1 < nk) { CP_WAIT(1); } else { CP_WAIT(0); }
        __syncthreads();
        if (ck + 2 < nk) issue((ck + 2) * 32, smb + ((ck + 2) % 3) * STAGE_B);

        const uint32_t sbase = smb + (ck % 3) * STAGE_B;
#pragma unroll
        for (int ks = 0; ks < 2; ks++) {
            uint32_t af[4][4], bf[8][2];
#pragma unroll
            for (int mt = 0; mt < 4; mt++)
                LDSM4(af[mt][0], af[mt][1], af[mt][2], af[mt][3],
                      sbase + a_ld + (mt * 16 * PITCH + ks * 16) * 2);
#pragma unroll
            for (int ntp = 0; ntp < 4; ntp++)
                LDSM4(bf[2 * ntp][0], bf[2 * ntp][1],
                      bf[2 * ntp + 1][0], bf[2 * ntp + 1][1],
                      sbase + b_ld + (ntp * 16 * PITCH + ks * 16) * 2);
#pragma unroll
            for (int mt = 0; mt < 4; mt++)
#pragma unroll
                for (int nt = 0; nt < 8; nt++) mma16(acc[mt][nt], af[mt], bf[nt]);
        }
    }

#pragma unroll
    for (int mt = 0; mt < 4; mt++) {
        const int r = m0 + wm * 64 + mt * 16 + lg;
#pragma unroll
        for (int nt = 0; nt < 8; nt++) {
            const int n = n0 + wn * 64 + nt * 8 + 2 * lt;
            float4 v = acc[mt][nt];
            if (DO_EXP) {
                v.x = __expf(v.x); v.y = __expf(v.y);
                v.z = __expf(v.z); v.w = __expf(v.w);
            }
            v.x *= outscale; v.y *= outscale; v.z *= outscale; v.w *= outscale;
            if (n < NB) {
                if (r < MA)
                    *(__half2*)(C + (long)r * ldc + n) = __floats2half2_rn(v.x, v.y);
                if (r + 8 < MA)
                    *(__half2*)(C + (long)(r + 8) * ldc + n) = __floats2half2_rn(v.z, v.w);
            }
        }
    }
}

// ---------------- conv 3x3 SAME via implicit GEMM (fp16 MMA, fp32 out) -------
__global__ void __launch_bounds__(128, 2)
conv_mma(const __half* __restrict__ attTe, const __half* __restrict__ attTq,
         const __half* __restrict__ wT, float* __restrict__ out)
{
    extern __shared__ __half sm[];
    const uint32_t smb = s2u(sm);
    const int tid = threadIdx.x;
    const int lane = tid & 31, wid = tid >> 5;
    const int wm = wid >> 1, wn = wid & 1;
    const int lg = lane >> 2, lt = lane & 3;
    const int z = blockIdx.z;
    const int b = z & 15, which = z >> 4;
    const __half* inT = (which ? attTq : attTe) + (long)b * N_PIX * CCH;
    const __half* wbase = wT + (long)which * 9 * CCH * CCH;
    const int m0 = blockIdx.y * 128;
    const int n0 = blockIdx.x * 128;

    const int lrow = tid >> 2;
    const int lf4  = tid & 3;
    const uint32_t dbase = lrow * (PITCH * 2) + lf4 * 16;

    const uint32_t a_ld = ((wm * 64 + (lane & 15)) * PITCH + (lane >> 4) * 8) * 2;
    const uint32_t b_ld = AT_H * 2 +
        ((wn * 64 + (lane & 7) + ((lane >> 4) << 3)) * PITCH
         + ((lane >> 3) & 1) * 8) * 2;

    int py_[4], px_[4];
    bool pv_[4];
#pragma unroll
    for (int it = 0; it < 4; it++) {
        int p = n0 + lrow + it * 32;
        py_[it] = p / 40; px_[it] = p % 40;
        pv_[it] = (p < N_PIX);
    }

    float4 acc[4][8];
#pragma unroll
    for (int i = 0; i < 4; i++)
#pragma unroll
        for (int j = 0; j < 8; j++) acc[i][j] = make_float4(0.f, 0.f, 0.f, 0.f);

    const int nk = 144;   // 9 kyx * 16 c-chunks

    auto issue = [&](int ck, uint32_t sa) {
        const int kyx = ck >> 4;
        const int cc = (ck & 15) * 32;
        const int dy = kyx / 3 - 1, dx = kyx % 3 - 1;
        const __half* wk = wbase + (long)kyx * (CCH * CCH) + cc
                           + (m0 + lrow) * CCH + lf4 * 8;
#pragma unroll
        for (int it = 0; it < 4; it++) {
            cpasync16(sa + dbase + it * (32 * PITCH * 2),
                      wk + it * (32 * CCH), 16u);
            int ys = py_[it] + dy, xs = px_[it] + dx;
            bool ok = pv_[it] && (unsigned)ys < 40u && (unsigned)xs < 40u;
            const __half* src = inT + (long)(ys * 40 + xs) * CCH + cc + lf4 * 8;
            cpasync16(sa + AT_H * 2 + dbase + it * (32 * PITCH * 2),
                      src, ok ? 16u : 0u);
        }
        CP_COMMIT();
    };

    issue(0, smb);
    issue(1, smb + STAGE_B);

    for (int ck = 0; ck < nk; ck++) {
        if (ck + 1 < nk) { CP_WAIT(1); } else { CP_WAIT(0); }
        __syncthreads();
        if (ck + 2 < nk) issue(ck + 2, smb + ((ck + 2) % 3) * STAGE_B);

        const uint32_t sbase = smb + (ck % 3) * STAGE_B;
#pragma unroll
        for (int ks = 0; ks < 2; ks++) {
            uint32_t af[4][4], bf[8][2];
#pragma unroll
            for (int mt = 0; mt < 4; mt++)
                LDSM4(af[mt][0], af[mt][1], af[mt][2], af[mt][3],
                      sbase + a_ld + (mt * 16 * PITCH + ks * 16) * 2);
#pragma unroll
            for (int ntp = 0; ntp < 4; ntp++)
                LDSM4(bf[2 * ntp][0], bf[2 * ntp][1],
                      bf[2 * ntp + 1][0], bf[2 * ntp + 1][1],
                      sbase + b_ld + (ntp * 16 * PITCH + ks * 16) * 2);
#pragma unroll
            for (int mt = 0; mt < 4; mt++)
#pragma unroll
                for (int nt = 0; nt < 8; nt++) mma16(acc[mt][nt], af[mt], bf[nt]);
        }
    }

    float* obase = out + ((long)b * 2 * CCH + (long)which * CCH) * N_PIX;
#pragma unroll
    for (int mt = 0; mt < 4; mt++) {
        const int r = m0 + wm * 64 + mt * 16 + lg;
#pragma unroll
        for (int nt = 0; nt < 8; nt++) {
            const int n = n0 + wn * 64 + nt * 8 + 2 * lt;
            if (n < N_PIX) {
                float4 v = acc[mt][nt];
                *(float2*)(obase + (long)r * N_PIX + n) = make_float2(v.x, v.y);
                *(float2*)(obase + (long)(r + 8) * N_PIX + n) = make_float2(v.z, v.w);
            }
        }
    }
}

// ------------- dual input transpose [c][p] -> [p][c], float -> half ----------
__global__ void transpose_in(const float* __restrict__ s0, __half* __restrict__ d0,
                             const float* __restrict__ s1, __half* __restrict__ d1)
{
    __shared__ float t[32][33];
    const int z = blockIdx.z;
    const int b = z & 15, which = z >> 4;
    const long CN = (long)CCH * N_PIX;
    const float* src = (which ? s1 : s0) + (long)b * CN;
    __half* dst = (which ? d1 : d0) + (long)b * CN;
    const int x0 = blockIdx.x * 32, y0 = blockIdx.y * 32;
    const int tx = threadIdx.x, ty = threadIdx.y;
#pragma unroll
    for (int r = 0; r < 32; r += 8)
        t[ty + r][tx] = src[(long)(y0 + ty + r) * N_PIX + x0 + tx];
    __syncthreads();
#pragma unroll
    for (int r = 0; r < 32; r += 8)
        dst[(long)(x0 + ty + r) * CCH + y0 + tx] = __float2half(t[tx][ty + r]);
}

// ------- E transpose (half) + per-tile row/col partial sums (float) ----------
__global__ void transpose_es(const __half* __restrict__ E, __half* __restrict__ Et,
                             float* __restrict__ prow, float* __restrict__ pcol)
{
    __shared__ __half t[32][34];
    const long NN = (long)N_PIX * N_PIX;
    const int bz = blockIdx.z;
    const __half* src = E + bz * NN;
    __half* dst = Et + bz * NN;
    const int x0 = blockIdx.x * 32, y0 = blockIdx.y * 32;
    const int tx = threadIdx.x, ty = threadIdx.y;   // (32, 8)
#pragma unroll
    for (int r = 0; r < 32; r += 8)
        t[ty + r][tx] = src[(long)(y0 + ty + r) * N_PIX + x0 + tx];
    __syncthreads();

    if (ty == 0) {
        float s = 0.f;
#pragma unroll 8
        for (int j = 0; j < 32; j++) s += __half2float(t[tx][j]);
        prow[((bz * NTILE) + blockIdx.x) * N_PIX + y0 + tx] = s;
    } else if (ty == 1) {
        float s = 0.f;
#pragma unroll 8
        for (int i = 0; i < 32; i++) s += __half2float(t[i][tx]);
        pcol[((bz * NTILE) + blockIdx.y) * N_PIX + x0 + tx] = s;
    }
#pragma unroll
    for (int r = 0; r < 32; r += 8)
        dst[(long)(x0 + ty + r) * N_PIX + y0 + tx] = t[tx][ty + r];
}

// ------------- reduce partials over 50 tiles and invert ----------------------
__global__ void reduce_inv(const float* __restrict__ prow,
                           const float* __restrict__ pcol,
                           float* __restrict__ rsE, float* __restrict__ rsEt)
{
    int idx = blockIdx.x * 256 + threadIdx.x;
    if (idx >= BATCH * N_PIX) return;
    const int b = idx / N_PIX, n = idx % N_PIX;
    const float* src = (blockIdx.y ? pcol : prow) + (long)b * NTILE * N_PIX + n;
    float s = 0.f;
#pragma unroll 10
    for (int tgt = 0; tgt < NTILE; tgt++) s += src[(long)tgt * N_PIX];
    (blockIdx.y ? rsEt : rsE)[idx] = 1.f / s;
}

// esc = exemplar*invColsum*4096; qsc = query*invRowsum*4096 (half out) --------
__global__ void scale_kernel(const float* __restrict__ ex,
                             const float* __restrict__ qu,
                             const float* __restrict__ invCs,
                             const float* __restrict__ invRs,
                             __half* __restrict__ e2, __half* __restrict__ q2)
{
    long idx = (long)blockIdx.x * 256 + threadIdx.x;
    if (idx >= (long)BATCH * CCH * N_PIX) return;
    int i = (int)(idx % N_PIX);
    int b = (int)(idx / ((long)CCH * N_PIX));
    e2[idx] = __float2half(ex[idx] * (invCs[b * N_PIX + i] * ESCALE));
    q2[idx] = __float2half(qu[idx] * (invRs[b * N_PIX + i] * ESCALE));
}

// ---------------- conv weights OIHW -> [which][kyx][o][c] (half) -------------
__global__ void wtrans_kernel(const float* __restrict__ w1,
                              const float* __restrict__ w2,
                              __half* __restrict__ wT)
{
    long idx = (long)blockIdx.x * 256 + threadIdx.x;
    const long per = 9L * CCH * CCH;
    if (idx >= 2 * per) return;
    int c = (int)(idx & (CCH - 1));
    long t = idx >> 9;
    int o = (int)(t & (CCH - 1));
    long t2 = t >> 9;
    int kyx = (int)(t2 % 9);
    int which = (int)(t2 / 9);
    const float* w = which ? w2 : w1;
    wT[idx] = __float2half(w[((long)o * CCH + c) * 9 + kyx]);
}

// ---------------- 1x1 weights: copy w_q, w_e to half --------------------------
__global__ void w1cvt_kernel(const float* __restrict__ wq,
                             const float* __restrict__ we,
                             __half* __restrict__ dst)
{
    int idx = blockIdx.x * 256 + threadIdx.x;
    if (idx >= 2 * CORR * CCH) return;
    const float* w = (idx < CORR * CCH) ? wq : we;
    dst[idx] = __float2half(w[idx < CORR * CCH ? idx : idx - CORR * CCH]);
}

// ---------------- launch ------------------------------------------------------
extern "C" void kernel_launch(void* const* d_in, const int* in_sizes, int n_in,
                              void* d_out, int out_size)
{
    const float* exemplar = (const float*)d_in[0];
    const float* query    = (const float*)d_in[1];
    const float* w_e      = (const float*)d_in[2];
    const float* w_q      = (const float*)d_in[3];
    const float* w_c1     = (const float*)d_in[4];
    const float* w_c2     = (const float*)d_in[5];
    float* out = (float*)d_out;

    __half *inTe, *inTq, *qcorr, *ecorr, *E, *Et, *esc, *qsc, *attTe, *attTq, *wT, *w1;
    float *prow, *pcol, *rsE, *rsEt;
    cudaGetSymbolAddress((void**)&inTe,  g_inTe);
    cudaGetSymbolAddress((void**)&inTq,  g_inTq);
    cudaGetSymbolAddress((void**)&qcorr, g_qcorr);
    cudaGetSymbolAddress((void**)&ecorr, g_ecorr);
    cudaGetSymbolAddress((void**)&E,     g_E);
    cudaGetSymbolAddress((void**)&Et,    g_Et);
    cudaGetSymbolAddress((void**)&prow,  g_prow);
    cudaGetSymbolAddress((void**)&pcol,  g_pcol);
    cudaGetSymbolAddress((void**)&rsE,   g_rsE);
    cudaGetSymbolAddress((void**)&rsEt,  g_rsEt);
    cudaGetSymbolAddress((void**)&esc,   g_esc);
    cudaGetSymbolAddress((void**)&qsc,   g_qsc);
    cudaGetSymbolAddress((void**)&attTe, g_attTe);
    cudaGetSymbolAddress((void**)&attTq, g_attTq);
    cudaGetSymbolAddress((void**)&wT,    g_wT);
    cudaGetSymbolAddress((void**)&w1,    g_w1);

    cudaFuncSetAttribute(gemm_mma<false>,
                         cudaFuncAttributeMaxDynamicSharedMemorySize, SMEM_B);
    cudaFuncSetAttribute(gemm_mma<true>,
                         cudaFuncAttributeMaxDynamicSharedMemorySize, SMEM_B);
    cudaFuncSetAttribute(conv_mma,
                         cudaFuncAttributeMaxDynamicSharedMemorySize, SMEM_B);

    // one-time host-side stream/event setup (no device allocation APIs)
    static cudaStream_t s1 = nullptr;
    static cudaEvent_t ev[6];
    if (!s1) {
        cudaStreamCreateWithFlags(&s1, cudaStreamNonBlocking);
        for (int i = 0; i < 6; i++)
            cudaEventCreateWithFlags(&ev[i], cudaEventDisableTiming);
    }
    const cudaStream_t s0 = 0;   // captured (legacy) stream

    const long NN = (long)N_PIX * N_PIX;
    const long CN = (long)CCH * N_PIX;
    const long NK = (long)N_PIX * CORR;

    // ---- fork: transpose_in on s1, weight re-layouts on s0 ------------------
    cudaEventRecord(ev[0], s0);
    cudaStreamWaitEvent(s1, ev[0], 0);
    transpose_in<<<dim3(NTILE, 16, 32), dim3(32, 8), 0, s1>>>(
        exemplar, inTe, query, inTq);
    wtrans_kernel<<<(unsigned)((2L * 9 * CCH * CCH + 255) / 256), 256, 0, s0>>>(
        w_c1, w_c2, wT);
    w1cvt_kernel<<<(2 * CORR * CCH + 255) / 256, 256, 0, s0>>>(w_q, w_e, w1);

    // proj_e runs on s1 (after transpose_in, and after w1 via event)
    cudaEventRecord(ev[1], s0);
    cudaStreamWaitEvent(s1, ev[1], 0);
    gemm_mma<false><<<dim3(2, 13, BATCH), 128, SMEM_B, s1>>>(
        inTe, w1 + (long)CORR * CCH, ecorr, CCH, N_PIX, CORR, CORR, CN, 0L, NK, 1.0f);
    // proj_q runs on s0 (needs transpose_in from s1)
    cudaEventRecord(ev[2], s1);   // marks transpose_in (+proj_e issued; order ok)
    cudaStreamWaitEvent(s0, ev[2], 0);
    gemm_mma<false><<<dim3(2, 13, BATCH), 128, SMEM_B, s0>>>(
        inTq, w1, qcorr, CCH, N_PIX, CORR, CORR, CN, 0L, NK, 1.0f);

    // join: E gemm needs both projections
    cudaEventRecord(ev[3], s1);
    cudaStreamWaitEvent(s0, ev[3], 0);

    // E[n][m] = exp( sum_k ecorr[n][k] * qcorr[m][k] )
    gemm_mma<true><<<dim3(13, 13, BATCH), 128, SMEM_B, s0>>>(
        ecorr, qcorr, E, CORR, N_PIX, N_PIX, N_PIX, NK, NK, NN, 1.0f);

    // Et = E^T, fused per-tile row/col partial sums
    transpose_es<<<dim3(NTILE, NTILE, BATCH), dim3(32, 8), 0, s0>>>(E, Et, prow, pcol);
    reduce_inv<<<dim3((BATCH * N_PIX + 255) / 256, 2), 256, 0, s0>>>(
        prow, pcol, rsE, rsEt);
    scale_kernel<<<(unsigned)(((long)BATCH * CCH * N_PIX + 255) / 256), 256, 0, s0>>>(
        exemplar, query, rsEt, rsE, esc, qsc);

    // ---- fork: the two attention GEMMs run concurrently ---------------------
    cudaEventRecord(ev[4], s0);
    cudaStreamWaitEvent(s1, ev[4], 0);
    gemm_mma<false><<<dim3(4, 13, BATCH), 128, SMEM_B, s1>>>(
        Et, qsc, attTe, N_PIX, N_PIX, CCH, CCH, NN, CN, CN, INV_ESCALE);
    gemm_mma<false><<<dim3(4, 13, BATCH), 128, SMEM_B, s0>>>(
        E, esc, attTq, N_PIX, N_PIX, CCH, CCH, NN, CN, CN, INV_ESCALE);
    cudaEventRecord(ev[5], s1);
    cudaStreamWaitEvent(s0, ev[5], 0);

    // 3x3 SAME convs into concatenated output
    conv_mma<<<dim3(13, 4, 2 * BATCH), 128, SMEM_B, s0>>>(attTe, attTq, wT, out);
}

// round 17
// speedup vs baseline: 1.1826x; 1.0150x over previous
#include <cuda_runtime.h>
#include <cuda_fp16.h>
#include <cstdint>

#define N_PIX 1600
#define CCH   512
#define CORR  256
#define BATCH 16
#define NTILE 50    // N_PIX / 32

#define ESCALE 4096.0f
#define INV_ESCALE (1.0f / 4096.0f)

// ---------------- scratch (static __device__ arrays; allocation-free) -------
__device__ __half g_inTe  [BATCH * N_PIX * CCH];           // exemplar^T [p][c]
__device__ __half g_inTq  [BATCH * N_PIX * CCH];           // query^T    [p][c]
__device__ __half g_qcorr [BATCH * N_PIX * CORR];
__device__ __half g_ecorr [BATCH * N_PIX * CORR];
__device__ __half g_E     [(long)BATCH * N_PIX * N_PIX];   // exp(A)   82 MB
__device__ __half g_Et    [(long)BATCH * N_PIX * N_PIX];   // E^T      82 MB
__device__ float  g_prow  [BATCH * NTILE * N_PIX];
__device__ float  g_pcol  [BATCH * NTILE * N_PIX];
__device__ float  g_rsE   [BATCH * N_PIX];                 // 1/rowsum(E)
__device__ float  g_rsEt  [BATCH * N_PIX];                 // 1/colsum(E)
__device__ __half g_esc   [BATCH * CCH * N_PIX];           // exemplar*invColsum*4096
__device__ __half g_qsc   [BATCH * CCH * N_PIX];           // query*invRowsum*4096
__device__ __half g_attTe [BATCH * N_PIX * CCH];
__device__ __half g_attTq [BATCH * N_PIX * CCH];
__device__ __half g_wT    [2 * 9 * CCH * CCH];             // [which][kyx][o][c]
__device__ __half g_w1    [2 * CORR * CCH];

// ---------------- helpers -----------------------------------------------------
__device__ __forceinline__ void mma16(float4& d, const uint32_t a[4],
                                      const uint32_t b[2]) {
    asm volatile(
        "mma.sync.aligned.m16n8k16.row.col.f32.f16.f16.f32 "
        "{%0,%1,%2,%3}, {%4,%5,%6,%7}, {%8,%9}, {%0,%1,%2,%3};"
        : "+f"(d.x), "+f"(d.y), "+f"(d.z), "+f"(d.w)
        : "r"(a[0]), "r"(a[1]), "r"(a[2]), "r"(a[3]), "r"(b[0]), "r"(b[1]));
}
#define LDSM4(r0, r1, r2, r3, addr) \
    asm volatile("ldmatrix.sync.aligned.m8n8.x4.shared.b16 {%0,%1,%2,%3}, [%4];" \
                 : "=r"(r0), "=r"(r1), "=r"(r2), "=r"(r3) : "r"(addr))

__device__ __forceinline__ uint32_t s2u(const void* p) {
    return (uint32_t)__cvta_generic_to_shared(p);
}
__device__ __forceinline__ void cpasync16(uint32_t dst, const void* src,
                                          uint32_t sz) {
    asm volatile("cp.async.cg.shared.global [%0], [%1], 16, %2;"
                 :: "r"(dst), "l"(src), "r"(sz));
}
#define CP_COMMIT() asm volatile("cp.async.commit_group;" ::: "memory")
#define CP_WAIT(n)  asm volatile("cp.async.wait_group %0;" :: "n"(n) : "memory")

// smem geometry (halfs): CTA tile 128x128, k-chunk 32 halfs, THREE stages
#define PITCH    40                      // halfs; 80B rows -> LDSM conflict-free
#define AT_H     (128 * PITCH)           // 5120 halfs per operand tile
#define STAGE_H  (2 * AT_H)              // 10240
#define STAGE_B  (STAGE_H * 2)           // 20480 bytes
#define SMEM_B   (3 * STAGE_B)           // 61440 bytes

// ================= shared mainloop body (R10 best config) =====================
// Included into each kernel as a macro-free sequence via a device function that
// takes resolved pointers; kept flat to preserve R10 codegen.
template<bool DO_EXP>
__device__ __forceinline__ void gemm_body(
    const __half* __restrict__ A, const __half* __restrict__ B,
    __half* __restrict__ C, int K, int MA, int NB, int ldc, float outscale,
    __half* sm, int m0, int n0)
{
    const uint32_t smb = s2u(sm);
    const int tid = threadIdx.x;
    const int lane = tid & 31, wid = tid >> 5;
    const int wm = wid >> 1, wn = wid & 1;
    const int lg = lane >> 2, lt = lane & 3;

    const int lrow = tid >> 2;          // 0..31
    const int lf4  = tid & 3;

    const __half* Abase = A + (long)(m0 + lrow) * K + lf4 * 8;
    const __half* Bbase = B + (long)(n0 + lrow) * K + lf4 * 8;
    const uint32_t dbase = lrow * (PITCH * 2) + lf4 * 16;

    const uint32_t a_ld = ((wm * 64 + (lane & 15)) * PITCH + (lane >> 4) * 8) * 2;
    const uint32_t b_ld = AT_H * 2 +
        ((wn * 64 + (lane & 7) + ((lane >> 4) << 3)) * PITCH
         + ((lane >> 3) & 1) * 8) * 2;

    float4 acc[4][8];
#pragma unroll
    for (int i = 0; i < 4; i++)
#pragma unroll
        for (int j = 0; j < 8; j++) acc[i][j] = make_float4(0.f, 0.f, 0.f, 0.f);

    const int nk = K >> 5;

    auto issue = [&](int koff, uint32_t sa) {
#pragma unroll
        for (int it = 0; it < 4; it++) {
            const int row = lrow + it * 32;
            cpasync16(sa + dbase + it * (32 * PITCH * 2),
                      Abase + (long)(it * 32) * K + koff,
                      (m0 + row) < MA ? 16u : 0u);
            cpasync16(sa + AT_H * 2 + dbase + it * (32 * PITCH * 2),
                      Bbase + (long)(it * 32) * K + koff,
                      (n0 + row) < NB ? 16u : 0u);
        }
        CP_COMMIT();
    };

    issue(0, smb);
    if (nk > 1) issue(32, smb + STAGE_B);

    for (int ck = 0; ck < nk; ck++) {
        if (ck + 1 < nk) { CP_WAIT(1); } else { CP_WAIT(0); }
        __syncthreads();
        if (ck + 2 < nk) issue((ck + 2) * 32, smb + ((ck + 2) % 3) * STAGE_B);

        const uint32_t sbase = smb + (ck % 3) * STAGE_B;
#pragma unroll
        for (int ks = 0; ks < 2; ks++) {
            uint32_t af[4][4], bf[8][2];
#pragma unroll
            for (int mt = 0; mt < 4; mt++)
                LDSM4(af[mt][0], af[mt][1], af[mt][2], af[mt][3],
                      sbase + a_ld + (mt * 16 * PITCH + ks * 16) * 2);
#pragma unroll
            for (int ntp = 0; ntp < 4; ntp++)
                LDSM4(bf[2 * ntp][0], bf[2 * ntp][1],
                      bf[2 * ntp + 1][0], bf[2 * ntp + 1][1],
                      sbase + b_ld + (ntp * 16 * PITCH + ks * 16) * 2);
#pragma unroll
            for (int mt = 0; mt < 4; mt++)
#pragma unroll
                for (int nt = 0; nt < 8; nt++) mma16(acc[mt][nt], af[mt], bf[nt]);
        }
    }

#pragma unroll
    for (int mt = 0; mt < 4; mt++) {
        const int r = m0 + wm * 64 + mt * 16 + lg;
#pragma unroll
        for (int nt = 0; nt < 8; nt++) {
            const int n = n0 + wn * 64 + nt * 8 + 2 * lt;
            float4 v = acc[mt][nt];
            if (DO_EXP) {
                v.x = __expf(v.x); v.y = __expf(v.y);
                v.z = __expf(v.z); v.w = __expf(v.w);
            }
            v.x *= outscale; v.y *= outscale; v.z *= outscale; v.w *= outscale;
            if (n < NB) {
                if (r < MA)
                    *(__half2*)(C + (long)r * ldc + n) = __floats2half2_rn(v.x, v.y);
                if (r + 8 < MA)
                    *(__half2*)(C + (long)(r + 8) * ldc + n) = __floats2half2_rn(v.z, v.w);
            }
        }
    }
}

// -------- single-source GEMM (E = exp(...)) -----------------------------------
template<bool DO_EXP>
__global__ void __launch_bounds__(128, 2)
gemm_mma(const __half* __restrict__ A, const __half* __restrict__ B,
         __half* __restrict__ C, int K, int MA, int NB, int ldc,
         long bA, long bB, long bC, float outscale)
{
    extern __shared__ __half sm[];
    A += (long)blockIdx.z * bA;
    B += (long)blockIdx.z * bB;
    C += (long)blockIdx.z * bC;
    gemm_body<DO_EXP>(A, B, C, K, MA, NB, ldc, outscale, sm,
                      blockIdx.y * 128, blockIdx.x * 128);
}

// -------- dual-source GEMM: z = batch + 16*which (flat, conv-style select) ----
__global__ void __launch_bounds__(128, 2)
gemm_mma2(const __half* __restrict__ A0, const __half* __restrict__ B0,
          __half* __restrict__ C0, long bA0, long bB0, long bC0,
          const __half* __restrict__ A1, const __half* __restrict__ B1,
          __half* __restrict__ C1, long bA1, long bB1, long bC1,
          int K, int MA, int NB, int ldc, float outscale)
{
    extern __shared__ __half sm[];
    const int z = blockIdx.z;
    const int b = z & 15, which = z >> 4;
    const __half* A = which ? (A1 + (long)b * bA1) : (A0 + (long)b * bA0);
    const __half* B = which ? (B1 + (long)b * bB1) : (B0 + (long)b * bB0);
    __half* C       = which ? (C1 + (long)b * bC1) : (C0 + (long)b * bC0);
    gemm_body<false>(A, B, C, K, MA, NB, ldc, outscale, sm,
                     blockIdx.y * 128, blockIdx.x * 128);
}

// ---------------- conv 3x3 SAME via implicit GEMM (fp16 MMA, fp32 out) -------
__global__ void __launch_bounds__(128, 2)
conv_mma(const __half* __restrict__ attTe, const __half* __restrict__ attTq,
         const __half* __restrict__ wT, float* __restrict__ out)
{
    extern __shared__ __half sm[];
    const uint32_t smb = s2u(sm);
    const int tid = threadIdx.x;
    const int lane = tid & 31, wid = tid >> 5;
    const int wm = wid >> 1, wn = wid & 1;
    const int lg = lane >> 2, lt = lane & 3;
    const int z = blockIdx.z;
    const int b = z & 15, which = z >> 4;
    const __half* inT = (which ? attTq : attTe) + (long)b * N_PIX * CCH;
    const __half* wbase = wT + (long)which * 9 * CCH * CCH;
    const int m0 = blockIdx.y * 128;
    const int n0 = blockIdx.x * 128;

    const int lrow = tid >> 2;
    const int lf4  = tid & 3;
    const uint32_t dbase = lrow * (PITCH * 2) + lf4 * 16;

    const uint32_t a_ld = ((wm * 64 + (lane & 15)) * PITCH + (lane >> 4) * 8) * 2;
    const uint32_t b_ld = AT_H * 2 +
        ((wn * 64 + (lane & 7) + ((lane >> 4) << 3)) * PITCH
         + ((lane >> 3) & 1) * 8) * 2;

    int py_[4], px_[4];
    bool pv_[4];
#pragma unroll
    for (int it = 0; it < 4; it++) {
        int p = n0 + lrow + it * 32;
        py_[it] = p / 40; px_[it] = p % 40;
        pv_[it] = (p < N_PIX);
    }

    float4 acc[4][8];
#pragma unroll
    for (int i = 0; i < 4; i++)
#pragma unroll
        for (int j = 0; j < 8; j++) acc[i][j] = make_float4(0.f, 0.f, 0.f, 0.f);

    const int nk = 144;   // 9 kyx * 16 c-chunks

    auto issue = [&](int ck, uint32_t sa) {
        const int kyx = ck >> 4;
        const int cc = (ck & 15) * 32;
        const int dy = kyx / 3 - 1, dx = kyx % 3 - 1;
        const __half* wk = wbase + (long)kyx * (CCH * CCH) + cc
                           + (m0 + lrow) * CCH + lf4 * 8;
#pragma unroll
        for (int it = 0; it < 4; it++) {
            cpasync16(sa + dbase + it * (32 * PITCH * 2),
                      wk + it * (32 * CCH), 16u);
            int ys = py_[it] + dy, xs = px_[it] + dx;
            bool ok = pv_[it] && (unsigned)ys < 40u && (unsigned)xs < 40u;
            const __half* src = inT + (long)(ys * 40 + xs) * CCH + cc + lf4 * 8;
            cpasync16(sa + AT_H * 2 + dbase + it * (32 * PITCH * 2),
                      src, ok ? 16u : 0u);
        }
        CP_COMMIT();
    };

    issue(0, smb);
    issue(1, smb + STAGE_B);

    for (int ck = 0; ck < nk; ck++) {
        if (ck + 1 < nk) { CP_WAIT(1); } else { CP_WAIT(0); }
        __syncthreads();
        if (ck + 2 < nk) issue(ck + 2, smb + ((ck + 2) % 3) * STAGE_B);

        const uint32_t sbase = smb + (ck % 3) * STAGE_B;
#pragma unroll
        for (int ks = 0; ks < 2; ks++) {
            uint32_t af[4][4], bf[8][2];
#pragma unroll
            for (int mt = 0; mt < 4; mt++)
                LDSM4(af[mt][0], af[mt][1], af[mt][2], af[mt][3],
                      sbase + a_ld + (mt * 16 * PITCH + ks * 16) * 2);
#pragma unroll
            for (int ntp = 0; ntp < 4; ntp++)
                LDSM4(bf[2 * ntp][0], bf[2 * ntp][1],
                      bf[2 * ntp + 1][0], bf[2 * ntp + 1][1],
                      sbase + b_ld + (ntp * 16 * PITCH + ks * 16) * 2);
#pragma unroll
            for (int mt = 0; mt < 4; mt++)
#pragma unroll
                for (int nt = 0; nt < 8; nt++) mma16(acc[mt][nt], af[mt], bf[nt]);
        }
    }

    float* obase = out + ((long)b * 2 * CCH + (long)which * CCH) * N_PIX;
#pragma unroll
    for (int mt = 0; mt < 4; mt++) {
        const int r = m0 + wm * 64 + mt * 16 + lg;
#pragma unroll
        for (int nt = 0; nt < 8; nt++) {
            const int n = n0 + wn * 64 + nt * 8 + 2 * lt;
            if (n < N_PIX) {
                float4 v = acc[mt][nt];
                *(float2*)(obase + (long)r * N_PIX + n) = make_float2(v.x, v.y);
                *(float2*)(obase + (long)(r + 8) * N_PIX + n) = make_float2(v.z, v.w);
            }
        }
    }
}

// ------------- dual input transpose [c][p] -> [p][c], float -> half ----------
__global__ void transpose_in(const float* __restrict__ s0, __half* __restrict__ d0,
                             const float* __restrict__ s1, __half* __restrict__ d1)
{
    __shared__ float t[32][33];
    const int z = blockIdx.z;
    const int b = z & 15, which = z >> 4;
    const long CN = (long)CCH * N_PIX;
    const float* src = (which ? s1 : s0) + (long)b * CN;
    __half* dst = (which ? d1 : d0) + (long)b * CN;
    const int x0 = blockIdx.x * 32, y0 = blockIdx.y * 32;
    const int tx = threadIdx.x, ty = threadIdx.y;
#pragma unroll
    for (int r = 0; r < 32; r += 8)
        t[ty + r][tx] = src[(long)(y0 + ty + r) * N_PIX + x0 + tx];
    __syncthreads();
#pragma unroll
    for (int r = 0; r < 32; r += 8)
        dst[(long)(x0 + ty + r) * CCH + y0 + tx] = __float2half(t[tx][ty + r]);
}

// ------- E transpose (half) + per-tile row/col partial sums (float) ----------
__global__ void transpose_es(const __half* __restrict__ E, __half* __restrict__ Et,
                             float* __restrict__ prow, float* __restrict__ pcol)
{
    __shared__ __half t[32][34];
    const long NN = (long)N_PIX * N_PIX;
    const int bz = blockIdx.z;
    const __half* src = E + bz * NN;
    __half* dst = Et + bz * NN;
    const int x0 = blockIdx.x * 32, y0 = blockIdx.y * 32;
    const int tx = threadIdx.x, ty = threadIdx.y;   // (32, 8)
#pragma unroll
    for (int r = 0; r < 32; r += 8)
        t[ty + r][tx] = src[(long)(y0 + ty + r) * N_PIX + x0 + tx];
    __syncthreads();

    if (ty == 0) {
        float s = 0.f;
#pragma unroll 8
        for (int j = 0; j < 32; j++) s += __half2float(t[tx][j]);
        prow[((bz * NTILE) + blockIdx.x) * N_PIX + y0 + tx] = s;
    } else if (ty == 1) {
        float s = 0.f;
#pragma unroll 8
        for (int i = 0; i < 32; i++) s += __half2float(t[i][tx]);
        pcol[((bz * NTILE) + blockIdx.y) * N_PIX + x0 + tx] = s;
    }
#pragma unroll
    for (int r = 0; r < 32; r += 8)
        dst[(long)(x0 + ty + r) * N_PIX + y0 + tx] = t[tx][ty + r];
}

// ------------- reduce partials over 50 tiles and invert ----------------------
__global__ void reduce_inv(const float* __restrict__ prow,
                           const float* __restrict__ pcol,
                           float* __restrict__ rsE, float* __restrict__ rsEt)
{
    int idx = blockIdx.x * 256 + threadIdx.x;
    if (idx >= BATCH * N_PIX) return;
    const int b = idx / N_PIX, n = idx % N_PIX;
    const float* src = (blockIdx.y ? pcol : prow) + (long)b * NTILE * N_PIX + n;
    float s = 0.f;
#pragma unroll 10
    for (int tgt = 0; tgt < NTILE; tgt++) s += src[(long)tgt * N_PIX];
    (blockIdx.y ? rsEt : rsE)[idx] = 1.f / s;
}

// esc = exemplar*invColsum*4096; qsc = query*invRowsum*4096 (half out) --------
__global__ void scale_kernel(const float* __restrict__ ex,
                             const float* __restrict__ qu,
                             const float* __restrict__ invCs,
                             const float* __restrict__ invRs,
                             __half* __restrict__ e2, __half* __restrict__ q2)
{
    long idx = (long)blockIdx.x * 256 + threadIdx.x;
    if (idx >= (long)BATCH * CCH * N_PIX) return;
    int i = (int)(idx % N_PIX);
    int b = (int)(idx / ((long)CCH * N_PIX));
    e2[idx] = __float2half(ex[idx] * (invCs[b * N_PIX + i] * ESCALE));
    q2[idx] = __float2half(qu[idx] * (invRs[b * N_PIX + i] * ESCALE));
}

// ---------------- conv weights OIHW -> [which][kyx][o][c] (half) -------------
__global__ void wtrans_kernel(const float* __restrict__ w1,
                              const float* __restrict__ w2,
                              __half* __restrict__ wT)
{
    long idx = (long)blockIdx.x * 256 + threadIdx.x;
    const long per = 9L * CCH * CCH;
    if (idx >= 2 * per) return;
    int c = (int)(idx & (CCH - 1));
    long t = idx >> 9;
    int o = (int)(t & (CCH - 1));
    long t2 = t >> 9;
    int kyx = (int)(t2 % 9);
    int which = (int)(t2 / 9);
    const float* w = which ? w2 : w1;
    wT[idx] = __float2half(w[((long)o * CCH + c) * 9 + kyx]);
}

// ---------------- 1x1 weights: copy w_q, w_e to half --------------------------
__global__ void w1cvt_kernel(const float* __restrict__ wq,
                             const float* __restrict__ we,
                             __half* __restrict__ dst)
{
    int idx = blockIdx.x * 256 + threadIdx.x;
    if (idx >= 2 * CORR * CCH) return;
    const float* w = (idx < CORR * CCH) ? wq : we;
    dst[idx] = __float2half(w[idx < CORR * CCH ? idx : idx - CORR * CCH]);
}

// ---------------- launch ------------------------------------------------------
extern "C" void kernel_launch(void* const* d_in, const int* in_sizes, int n_in,
                              void* d_out, int out_size)
{
    const float* exemplar = (const float*)d_in[0];
    const float* query    = (const float*)d_in[1];
    const float* w_e      = (const float*)d_in[2];
    const float* w_q      = (const float*)d_in[3];
    const float* w_c1     = (const float*)d_in[4];
    const float* w_c2     = (const float*)d_in[5];
    float* out = (float*)d_out;

    __half *inTe, *inTq, *qcorr, *ecorr, *E, *Et, *esc, *qsc, *attTe, *attTq, *wT, *w1;
    float *prow, *pcol, *rsE, *rsEt;
    cudaGetSymbolAddress((void**)&inTe,  g_inTe);
    cudaGetSymbolAddress((void**)&inTq,  g_inTq);
    cudaGetSymbolAddress((void**)&qcorr, g_qcorr);
    cudaGetSymbolAddress((void**)&ecorr, g_ecorr);
    cudaGetSymbolAddress((void**)&E,     g_E);
    cudaGetSymbolAddress((void**)&Et,    g_Et);
    cudaGetSymbolAddress((void**)&prow,  g_prow);
    cudaGetSymbolAddress((void**)&pcol,  g_pcol);
    cudaGetSymbolAddress((void**)&rsE,   g_rsE);
    cudaGetSymbolAddress((void**)&rsEt,  g_rsEt);
    cudaGetSymbolAddress((void**)&esc,   g_esc);
    cudaGetSymbolAddress((void**)&qsc,   g_qsc);
    cudaGetSymbolAddress((void**)&attTe, g_attTe);
    cudaGetSymbolAddress((void**)&attTq, g_attTq);
    cudaGetSymbolAddress((void**)&wT,    g_wT);
    cudaGetSymbolAddress((void**)&w1,    g_w1);

    cudaFuncSetAttribute(gemm_mma<false>,
                         cudaFuncAttributeMaxDynamicSharedMemorySize, SMEM_B);
    cudaFuncSetAttribute(gemm_mma<true>,
                         cudaFuncAttributeMaxDynamicSharedMemorySize, SMEM_B);
    cudaFuncSetAttribute(gemm_mma2,
                         cudaFuncAttributeMaxDynamicSharedMemorySize, SMEM_B);
    cudaFuncSetAttribute(conv_mma,
                         cudaFuncAttributeMaxDynamicSharedMemorySize, SMEM_B);

    const long NN = (long)N_PIX * N_PIX;
    const long CN = (long)CCH * N_PIX;
    const long NK = (long)N_PIX * CORR;

    // [1] conv weight re-layout (half)
    wtrans_kernel<<<(unsigned)((2L * 9 * CCH * CCH + 255) / 256), 256>>>(w_c1, w_c2, wT);
    // [2] 1x1 weights to half
    w1cvt_kernel<<<(2 * CORR * CCH + 255) / 256, 256>>>(w_q, w_e, w1);
    // [3] input transposes [c][p] -> [p][c] (half), both in one launch
    transpose_in<<<dim3(NTILE, 16, 32), dim3(32, 8)>>>(exemplar, inTe, query, inTq);

    // [4] both 1x1 projections in ONE launch (z selects q/e operand set)
    gemm_mma2<<<dim3(2, 13, 32), 128, SMEM_B>>>(
        inTq, w1, qcorr, CN, 0L, NK,
        inTe, w1 + (long)CORR * CCH, ecorr, CN, 0L, NK,
        CCH, N_PIX, CORR, CORR, 1.0f);

    // [5] E[n][m] = exp( sum_k ecorr[n][k] * qcorr[m][k] )   <- ncu capture slot
    gemm_mma<true><<<dim3(13, 13, BATCH), 128, SMEM_B>>>(
        ecorr, qcorr, E, CORR, N_PIX, N_PIX, N_PIX, NK, NK, NN, 1.0f);

    // [6] Et = E^T, fused per-tile row/col partial sums
    transpose_es<<<dim3(NTILE, NTILE, BATCH), dim3(32, 8)>>>(E, Et, prow, pcol);
    // [7] reduce + invert
    reduce_inv<<<dim3((BATCH * N_PIX + 255) / 256, 2), 256>>>(prow, pcol, rsE, rsEt);
    // [8] scaled inputs
    scale_kernel<<<(unsigned)(((long)BATCH * CCH * N_PIX + 255) / 256), 256>>>(
        exemplar, query, rsEt, rsE, esc, qsc);

    // [9] both attention GEMMs in ONE launch:
    //   which0: attTq[j][c] = (sum_i E[j][i]  * esc[c][i]) / 4096
    //   which1: attTe[j][c] = (sum_i Et[j][i] * qsc[c][i]) / 4096
    gemm_mma2<<<dim3(4, 13, 32), 128, SMEM_B>>>(
        E,  esc, attTq, NN, CN, CN,
        Et, qsc, attTe, NN, CN, CN,
        N_PIX, N_PIX, CCH, CCH, INV_ESCALE);

    // [10] 3x3 SAME convs into concatenated output
    conv_mma<<<dim3(13, 4, 2 * BATCH), 128, SMEM_B>>>(attTe, attTq, wT, out);
}